// round 12
// baseline (speedup 1.0000x reference)
#include <cuda_runtime.h>
#include <cuda_bf16.h>
#include <stdint.h>

#define HH 16
#define SS 4096
#define DD 64

__device__ __align__(16) __nv_bfloat16 g_qhi[HH * SS * DD];
__device__ __align__(16) __nv_bfloat16 g_qlo[HH * SS * DD];
__device__ __align__(16) __nv_bfloat16 g_khi[HH * SS * DD];
__device__ __align__(16) __nv_bfloat16 g_klo[HH * SS * DD];
__device__ __align__(16) __nv_bfloat16 g_vthi[HH * DD * SS];
__device__ __align__(16) __nv_bfloat16 g_vtlo[HH * DD * SS];
__device__ __align__(16) unsigned char g_mask8[(size_t)SS * SS];
__device__ __align__(16) float g_outun[HH * SS * DD];
__device__ float g_se[(size_t)HH * 32 * SS];
__device__ float g_rowinv[HH * SS];

static __device__ __forceinline__ uint32_t smem_u32(const void* p) {
    uint32_t a;
    asm("{ .reg .u64 t; cvta.to.shared.u64 t, %1; cvt.u32.u64 %0, t; }" : "=r"(a) : "l"(p));
    return a;
}
static __device__ __forceinline__ void ldsm4(uint32_t* r, uint32_t a) {
    asm volatile("ldmatrix.sync.aligned.m8n8.x4.shared.b16 {%0,%1,%2,%3}, [%4];"
        : "=r"(r[0]), "=r"(r[1]), "=r"(r[2]), "=r"(r[3]) : "r"(a));
}
static __device__ __forceinline__ void mma16816(float* c, const uint32_t* a,
                                                uint32_t b0, uint32_t b1) {
    asm volatile("mma.sync.aligned.m16n8k16.row.col.f32.bf16.bf16.f32 "
        "{%0,%1,%2,%3}, {%4,%5,%6,%7}, {%8,%9}, {%0,%1,%2,%3};"
        : "+f"(c[0]), "+f"(c[1]), "+f"(c[2]), "+f"(c[3])
        : "r"(a[0]), "r"(a[1]), "r"(a[2]), "r"(a[3]), "r"(b0), "r"(b1));
}
static __device__ __forceinline__ void cp16(uint32_t s, const void* g) {
    asm volatile("cp.async.cg.shared.global [%0], [%1], 16;" :: "r"(s), "l"(g));
}
#define CP_COMMIT() asm volatile("cp.async.commit_group;" ::: "memory")
#define CP_WAIT(n)  asm volatile("cp.async.wait_group %0;" :: "n"(n) : "memory")

static __device__ __forceinline__ uint32_t packhi2(float a, float b,
                                                   float* ra, float* rb) {
    __nv_bfloat16 ha = __float2bfloat16(a), hb = __float2bfloat16(b);
    *ra = a - __bfloat162float(ha);
    *rb = b - __bfloat162float(hb);
    return ((uint32_t)__bfloat16_as_ushort(hb) << 16) | (uint32_t)__bfloat16_as_ushort(ha);
}
static __device__ __forceinline__ uint32_t packlo2(float ra, float rb) {
    return ((uint32_t)__bfloat16_as_ushort(__float2bfloat16(rb)) << 16) |
           (uint32_t)__bfloat16_as_ushort(__float2bfloat16(ra));
}

// ===================== converts =====================
__global__ __launch_bounds__(256) void convert_qk(const float* __restrict__ q,
                                                  const float* __restrict__ k) {
    int i = blockIdx.x * 256 + threadIdx.x;
    float fq = q[i] * 0.125f;
    __nv_bfloat16 qh = __float2bfloat16(fq);
    g_qhi[i] = qh; g_qlo[i] = __float2bfloat16(fq - __bfloat162float(qh));
    float fk = k[i];
    __nv_bfloat16 kh = __float2bfloat16(fk);
    g_khi[i] = kh; g_klo[i] = __float2bfloat16(fk - __bfloat162float(kh));
}
__global__ __launch_bounds__(256) void convert_v(const float* __restrict__ v) {
    __shared__ __nv_bfloat16 th[64][65], tl[64][65];
    const int h = blockIdx.y, s0 = blockIdx.x * 64, tid = threadIdx.x;
#pragma unroll
    for (int j = 0; j < 16; j++) {
        int i = tid + j * 256, sr = i >> 6, d = i & 63;
        float f = v[((size_t)(h * SS + s0 + sr)) * DD + d];
        __nv_bfloat16 hi = __float2bfloat16(f);
        th[sr][d] = hi; tl[sr][d] = __float2bfloat16(f - __bfloat162float(hi));
    }
    __syncthreads();
#pragma unroll
    for (int j = 0; j < 16; j++) {
        int i = tid + j * 256, d = i >> 6, sr = i & 63;
        size_t o = ((size_t)(h * DD + d)) * SS + s0 + sr;
        g_vthi[o] = th[sr][d]; g_vtlo[o] = tl[sr][d];
    }
}
__global__ __launch_bounds__(256) void convert_mask(const int* __restrict__ m) {
    size_t i = ((size_t)blockIdx.x * 256 + threadIdx.x) * 4;
    int4 v = *(const int4*)(m + i);
    uchar4 b;
    b.x = v.x ? 1 : 0; b.y = v.y ? 1 : 0; b.z = v.z ? 1 : 0; b.w = v.w ? 1 : 0;
    *(uchar4*)(g_mask8 + i) = b;
}

// ===================== fused kernel smem =====================
#define F_QHI 0
#define F_K0  36864
#define F_K1  73728
#define F_V0  110592
#define F_V1  145408
#define F_M0  180224
#define F_M1  198656
#define F_BYTES 217088

__global__ __launch_bounds__(256) void fused_attn(float* __restrict__ attn) {
    extern __shared__ char sm[];
    const uint32_t sb = smem_u32(sm);
    const int h = blockIdx.x, q0 = blockIdx.y * 128, tid = threadIdx.x;
    const int wid = tid >> 5, lane = tid & 31;
    const int lr = lane & 15, lc = lane >> 4;
    const int lam = lane & 3, r4 = lane >> 2;

    {   // prefetch tile 0
        const __nv_bfloat16* kh = g_khi + ((size_t)(h * SS)) * DD;
        const __nv_bfloat16* kl = g_klo + ((size_t)(h * SS)) * DD;
#pragma unroll
        for (int j = 0; j < 4; j++) {
            int i = tid + j * 256, row = i >> 3, u = i & 7;
            cp16(sb + F_K0 + row * 144 + u * 16, kh + row * DD + u * 8);
            cp16(sb + F_K0 + 18432 + row * 144 + u * 16, kl + row * DD + u * 8);
        }
#pragma unroll
        for (int j = 0; j < 4; j++) {
            int i = tid + j * 256, d = i >> 4, u = i & 15;
            size_t go = ((size_t)(h * DD + d)) * SS + u * 8;
            cp16(sb + F_V0 + d * 272 + u * 16, g_vthi + go);
            cp16(sb + F_V0 + 17408 + d * 272 + u * 16, g_vtlo + go);
        }
#pragma unroll
        for (int j = 0; j < 4; j++) {
            int i = tid + j * 256, row = i >> 3, u = i & 7;
            cp16(sb + F_M0 + row * 144 + u * 16,
                 g_mask8 + (size_t)(q0 + row) * SS + u * 16);
        }
        CP_COMMIT();
    }
    {   // persistent Q tile
        const __nv_bfloat16* qh = g_qhi + ((size_t)(h * SS + q0)) * DD;
        const __nv_bfloat16* ql = g_qlo + ((size_t)(h * SS + q0)) * DD;
#pragma unroll
        for (int j = 0; j < 4; j++) {
            int i = tid + j * 256, row = i >> 3, u = i & 7;
            *(uint4*)(sm + F_QHI + row * 144 + u * 16) = *(const uint4*)(qh + row * DD + u * 8);
            *(uint4*)(sm + F_QHI + 18432 + row * 144 + u * 16) = *(const uint4*)(ql + row * DD + u * 8);
        }
    }

    const uint32_t qa = sb + F_QHI + (uint32_t)(wid * 16 + lr) * 144 + lc * 16;
    float oacc[8][4];
#pragma unroll
    for (int n = 0; n < 8; n++)
#pragma unroll
        for (int c = 0; c < 4; c++) oacc[n][c] = 0.f;

    for (int kt = 0; kt < 32; kt++) {
        CP_WAIT(0);
        __syncthreads();
        if (kt < 31) {  // prefetch kt+1
            const int kn = (kt + 1) * 128;
            const int nb = (kt + 1) & 1;
            const uint32_t kb = sb + (nb ? F_K1 : F_K0);
            const uint32_t vb = sb + (nb ? F_V1 : F_V0);
            const uint32_t mb = sb + (nb ? F_M1 : F_M0);
            const __nv_bfloat16* kh = g_khi + ((size_t)(h * SS + kn)) * DD;
            const __nv_bfloat16* kl = g_klo + ((size_t)(h * SS + kn)) * DD;
#pragma unroll
            for (int j = 0; j < 4; j++) {
                int i = tid + j * 256, row = i >> 3, u = i & 7;
                cp16(kb + row * 144 + u * 16, kh + row * DD + u * 8);
                cp16(kb + 18432 + row * 144 + u * 16, kl + row * DD + u * 8);
            }
#pragma unroll
            for (int j = 0; j < 4; j++) {
                int i = tid + j * 256, d = i >> 4, u = i & 15;
                size_t go = ((size_t)(h * DD + d)) * SS + kn + u * 8;
                cp16(vb + d * 272 + u * 16, g_vthi + go);
                cp16(vb + 17408 + d * 272 + u * 16, g_vtlo + go);
            }
#pragma unroll
            for (int j = 0; j < 4; j++) {
                int i = tid + j * 256, row = i >> 3, u = i & 7;
                cp16(mb + row * 144 + u * 16,
                     g_mask8 + (size_t)(q0 + row) * SS + kn + u * 16);
            }
            CP_COMMIT();
        }
        const uint32_t kbase = sb + ((kt & 1) ? F_K1 : F_K0);
        const uint32_t vbase = sb + ((kt & 1) ? F_V1 : F_V0);
        const char* mbase = sm + ((kt & 1) ? F_M1 : F_M0);
        const int k0 = kt * 128;

        // ---- QK^T: dep-distance-8 MMA schedule ----
        float acc[16][4];
#pragma unroll
        for (int n = 0; n < 16; n++)
#pragma unroll
            for (int c = 0; c < 4; c++) acc[n][c] = 0.f;
#pragma unroll
        for (int ks = 0; ks < 4; ks++) {
            uint32_t ah[4], al[4];
            ldsm4(ah, qa + ks * 32);
            ldsm4(al, qa + 18432 + ks * 32);
#pragma unroll
            for (int hf = 0; hf < 2; hf++) {
                uint32_t bh[4][4], bl[4][4];
#pragma unroll
                for (int j = 0; j < 4; j++) {
                    const int cg = hf * 4 + j;
                    const uint32_t kadr = kbase + (uint32_t)(cg * 16 + lr) * 144 + lc * 16 + ks * 32;
                    ldsm4(bh[j], kadr);
                    ldsm4(bl[j], kadr + 18432);
                }
#pragma unroll
                for (int j = 0; j < 4; j++) {   // 8 independent hi*hi
                    mma16816(acc[2 * (hf * 4 + j)], ah, bh[j][0], bh[j][2]);
                    mma16816(acc[2 * (hf * 4 + j) + 1], ah, bh[j][1], bh[j][3]);
                }
#pragma unroll
                for (int j = 0; j < 4; j++) {   // 8 independent hi*lo
                    mma16816(acc[2 * (hf * 4 + j)], ah, bl[j][0], bl[j][2]);
                    mma16816(acc[2 * (hf * 4 + j) + 1], ah, bl[j][1], bl[j][3]);
                }
#pragma unroll
                for (int j = 0; j < 4; j++) {   // 8 independent lo*hi
                    mma16816(acc[2 * (hf * 4 + j)], al, bh[j][0], bh[j][2]);
                    mma16816(acc[2 * (hf * 4 + j) + 1], al, bh[j][1], bh[j][3]);
                }
            }
        }

        // ---- per 16-col group: exp -> attn STG -> reg A-frags -> PV ----
        const int rowl = wid * 16 + r4;
        float sA = 0.f, sB = 0.f;
#pragma unroll
        for (int cg = 0; cg < 8; cg++) {
            const int cb = cg * 16 + lam * 2;
            uchar2 mA0 = *(const uchar2*)(mbase + rowl * 144 + cb);
            uchar2 mA8 = *(const uchar2*)(mbase + rowl * 144 + cb + 8);
            uchar2 mB0 = *(const uchar2*)(mbase + (rowl + 8) * 144 + cb);
            uchar2 mB8 = *(const uchar2*)(mbase + (rowl + 8) * 144 + cb + 8);
            float eA0 = mA0.x ? 0.f : __expf(acc[2 * cg][0]);
            float eA1 = mA0.y ? 0.f : __expf(acc[2 * cg][1]);
            float eB0 = mB0.x ? 0.f : __expf(acc[2 * cg][2]);
            float eB1 = mB0.y ? 0.f : __expf(acc[2 * cg][3]);
            float eA8 = mA8.x ? 0.f : __expf(acc[2 * cg + 1][0]);
            float eA9 = mA8.y ? 0.f : __expf(acc[2 * cg + 1][1]);
            float eB8 = mB8.x ? 0.f : __expf(acc[2 * cg + 1][2]);
            float eB9 = mB8.y ? 0.f : __expf(acc[2 * cg + 1][3]);
            sA += (eA0 + eA1) + (eA8 + eA9);
            sB += (eB0 + eB1) + (eB8 + eB9);
            size_t base = ((size_t)(h * SS + q0 + rowl)) * SS + k0 + cb;
            *(float2*)(attn + base) = make_float2(eA0, eA1);
            *(float2*)(attn + base + 8) = make_float2(eA8, eA9);
            *(float2*)(attn + base + 8 * SS) = make_float2(eB0, eB1);
            *(float2*)(attn + base + 8 * SS + 8) = make_float2(eB8, eB9);
            float rA0, rA1, rB0, rB1, rA8, rA9, rB8, rB9;
            uint32_t pah[4], pal[4];
            pah[0] = packhi2(eA0, eA1, &rA0, &rA1);
            pah[1] = packhi2(eB0, eB1, &rB0, &rB1);
            pah[2] = packhi2(eA8, eA9, &rA8, &rA9);
            pah[3] = packhi2(eB8, eB9, &rB8, &rB9);
            pal[0] = packlo2(rA0, rA1);
            pal[1] = packlo2(rB0, rB1);
            pal[2] = packlo2(rA8, rA9);
            pal[3] = packlo2(rB8, rB9);
            // PV with dep-distance-8 schedule
            uint32_t vh[4][4], vl[4][4];
#pragma unroll
            for (int ng = 0; ng < 4; ng++) {
                const uint32_t vadr = vbase + (uint32_t)(ng * 16 + lr) * 272 + lc * 16 + cg * 32;
                ldsm4(vh[ng], vadr);
                ldsm4(vl[ng], vadr + 17408);
            }
#pragma unroll
            for (int ng = 0; ng < 4; ng++) {   // 8 independent ph*vh
                mma16816(oacc[2 * ng], pah, vh[ng][0], vh[ng][2]);
                mma16816(oacc[2 * ng + 1], pah, vh[ng][1], vh[ng][3]);
            }
#pragma unroll
            for (int ng = 0; ng < 4; ng++) {   // 8 independent ph*vl
                mma16816(oacc[2 * ng], pah, vl[ng][0], vl[ng][2]);
                mma16816(oacc[2 * ng + 1], pah, vl[ng][1], vl[ng][3]);
            }
#pragma unroll
            for (int ng = 0; ng < 4; ng++) {   // 8 independent pl*vh
                mma16816(oacc[2 * ng], pal, vh[ng][0], vh[ng][2]);
                mma16816(oacc[2 * ng + 1], pal, vh[ng][1], vh[ng][3]);
            }
        }
        sA += __shfl_xor_sync(~0u, sA, 1); sA += __shfl_xor_sync(~0u, sA, 2);
        sB += __shfl_xor_sync(~0u, sB, 1); sB += __shfl_xor_sync(~0u, sB, 2);
        if (lam == 0) {
            size_t so = ((size_t)(h * 32 + kt)) * SS + q0;
            g_se[so + rowl] = sA;
            g_se[so + rowl + 8] = sB;
        }
    }
    const int rowl = wid * 16 + r4;
#pragma unroll
    for (int nb = 0; nb < 8; nb++) {
        int col = nb * 8 + lam * 2;
        float* op = g_outun + ((size_t)(h * SS + q0 + rowl)) * DD + col;
        *(float2*)op = make_float2(oacc[nb][0], oacc[nb][1]);
        *(float2*)(op + 8 * DD) = make_float2(oacc[nb][2], oacc[nb][3]);
    }
}

// ===================== row inverse sums =====================
__global__ __launch_bounds__(256) void rowinv_kernel() {
    int idx = blockIdx.x * 256 + threadIdx.x;
    int h = idx >> 12, row = idx & 4095;
    float s = 0.f;
#pragma unroll 8
    for (int t = 0; t < 32; t++) s += g_se[((size_t)(h * 32 + t)) * SS + row];
    g_rowinv[idx] = 1.0f / s;
}

// ===================== normalize attn (stream) =====================
__global__ __launch_bounds__(256) void norm_attn(float* __restrict__ attn) {
    const int idx = blockIdx.x;
    const float ri = g_rowinv[idx];
    float4* p = (float4*)(attn + (size_t)idx * SS);
    const int tid = threadIdx.x;
#pragma unroll
    for (int i = 0; i < 4; i++) {
        float4 v = p[tid + i * 256];
        v.x *= ri; v.y *= ri; v.z *= ri; v.w *= ri;
        p[tid + i * 256] = v;
    }
}

// ===================== normalize out =====================
__global__ __launch_bounds__(256) void norm_out(float* __restrict__ out) {
    int i = blockIdx.x * 256 + threadIdx.x;
    out[i] = g_outun[i] * g_rowinv[i >> 6];
}

// ===================== launch =====================
extern "C" void kernel_launch(void* const* d_in, const int* in_sizes, int n_in,
                              void* d_out, int out_size) {
    const float* q = (const float*)d_in[0];
    const float* k = (const float*)d_in[1];
    const float* v = (const float*)d_in[2];
    const int* mask = (const int*)d_in[3];
    float* out = (float*)d_out;
    float* attn = out + (size_t)HH * SS * DD;

    cudaFuncSetAttribute(fused_attn, cudaFuncAttributeMaxDynamicSharedMemorySize, F_BYTES);

    convert_qk<<<(HH * SS * DD) / 256, 256>>>(q, k);
    convert_v<<<dim3(SS / 64, HH), 256>>>(v);
    convert_mask<<<(SS * SS) / 1024, 256>>>(mask);
    fused_attn<<<dim3(HH, SS / 128), 256, F_BYTES>>>(attn);
    rowinv_kernel<<<HH * SS / 256, 256>>>();
    norm_attn<<<HH * SS, 256>>>(attn);
    norm_out<<<HH * SS * DD / 256, 256>>>(out);
}

// round 13
// speedup vs baseline: 1.0614x; 1.0614x over previous
#include <cuda_runtime.h>
#include <cuda_bf16.h>
#include <stdint.h>

#define HH 16
#define SS 4096
#define DD 64

__device__ __align__(16) __nv_bfloat16 g_qhi[HH * SS * DD];
__device__ __align__(16) __nv_bfloat16 g_qlo[HH * SS * DD];
__device__ __align__(16) __nv_bfloat16 g_khi[HH * SS * DD];
__device__ __align__(16) __nv_bfloat16 g_klo[HH * SS * DD];
__device__ __align__(16) __nv_bfloat16 g_vthi[HH * DD * SS];
__device__ __align__(16) __nv_bfloat16 g_vtlo[HH * DD * SS];
__device__ __align__(16) unsigned char g_mask8[(size_t)SS * SS];
__device__ __align__(16) float g_outun[HH * SS * DD];
__device__ float g_se[(size_t)HH * 64 * SS];
__device__ float g_rowinv[HH * SS];

static __device__ __forceinline__ uint32_t smem_u32(const void* p) {
    uint32_t a;
    asm("{ .reg .u64 t; cvta.to.shared.u64 t, %1; cvt.u32.u64 %0, t; }" : "=r"(a) : "l"(p));
    return a;
}
static __device__ __forceinline__ void ldsm4(uint32_t* r, uint32_t a) {
    asm volatile("ldmatrix.sync.aligned.m8n8.x4.shared.b16 {%0,%1,%2,%3}, [%4];"
        : "=r"(r[0]), "=r"(r[1]), "=r"(r[2]), "=r"(r[3]) : "r"(a));
}
static __device__ __forceinline__ void mma16816(float* c, const uint32_t* a,
                                                uint32_t b0, uint32_t b1) {
    asm volatile("mma.sync.aligned.m16n8k16.row.col.f32.bf16.bf16.f32 "
        "{%0,%1,%2,%3}, {%4,%5,%6,%7}, {%8,%9}, {%0,%1,%2,%3};"
        : "+f"(c[0]), "+f"(c[1]), "+f"(c[2]), "+f"(c[3])
        : "r"(a[0]), "r"(a[1]), "r"(a[2]), "r"(a[3]), "r"(b0), "r"(b1));
}
static __device__ __forceinline__ void cp16(uint32_t s, const void* g) {
    asm volatile("cp.async.cg.shared.global [%0], [%1], 16;" :: "r"(s), "l"(g));
}
static __device__ __forceinline__ void cp8(uint32_t s, const void* g) {
    asm volatile("cp.async.ca.shared.global [%0], [%1], 8;" :: "r"(s), "l"(g));
}
#define CP_COMMIT() asm volatile("cp.async.commit_group;" ::: "memory")
#define CP_WAIT(n)  asm volatile("cp.async.wait_group %0;" :: "n"(n) : "memory")

static __device__ __forceinline__ uint32_t packhi2(float a, float b,
                                                   float* ra, float* rb) {
    __nv_bfloat16 ha = __float2bfloat16(a), hb = __float2bfloat16(b);
    *ra = a - __bfloat162float(ha);
    *rb = b - __bfloat162float(hb);
    return ((uint32_t)__bfloat16_as_ushort(hb) << 16) | (uint32_t)__bfloat16_as_ushort(ha);
}
static __device__ __forceinline__ uint32_t packlo2(float ra, float rb) {
    return ((uint32_t)__bfloat16_as_ushort(__float2bfloat16(rb)) << 16) |
           (uint32_t)__bfloat16_as_ushort(__float2bfloat16(ra));
}

// ===================== converts =====================
__global__ __launch_bounds__(256) void convert_qk(const float* __restrict__ q,
                                                  const float* __restrict__ k) {
    int i = blockIdx.x * 256 + threadIdx.x;
    float fq = q[i] * 0.125f;
    __nv_bfloat16 qh = __float2bfloat16(fq);
    g_qhi[i] = qh; g_qlo[i] = __float2bfloat16(fq - __bfloat162float(qh));
    float fk = k[i];
    __nv_bfloat16 kh = __float2bfloat16(fk);
    g_khi[i] = kh; g_klo[i] = __float2bfloat16(fk - __bfloat162float(kh));
}
__global__ __launch_bounds__(256) void convert_v(const float* __restrict__ v) {
    __shared__ __nv_bfloat16 th[64][65], tl[64][65];
    const int h = blockIdx.y, s0 = blockIdx.x * 64, tid = threadIdx.x;
#pragma unroll
    for (int j = 0; j < 16; j++) {
        int i = tid + j * 256, sr = i >> 6, d = i & 63;
        float f = v[((size_t)(h * SS + s0 + sr)) * DD + d];
        __nv_bfloat16 hi = __float2bfloat16(f);
        th[sr][d] = hi; tl[sr][d] = __float2bfloat16(f - __bfloat162float(hi));
    }
    __syncthreads();
#pragma unroll
    for (int j = 0; j < 16; j++) {
        int i = tid + j * 256, d = i >> 6, sr = i & 63;
        size_t o = ((size_t)(h * DD + d)) * SS + s0 + sr;
        g_vthi[o] = th[sr][d]; g_vtlo[o] = tl[sr][d];
    }
}
__global__ __launch_bounds__(256) void convert_mask(const int* __restrict__ m) {
    size_t i = ((size_t)blockIdx.x * 256 + threadIdx.x) * 4;
    int4 v = *(const int4*)(m + i);
    uchar4 b;
    b.x = v.x ? 1 : 0; b.y = v.y ? 1 : 0; b.z = v.z ? 1 : 0; b.w = v.w ? 1 : 0;
    *(uchar4*)(g_mask8 + i) = b;
}

// ===================== fused kernel smem (k-tile = 64, 90KB -> 2 blocks/SM) ==
#define F_K0  0        // K buf: hi 64x144 = 9216, lo at +9216 (18432 per buf)
#define F_K1  18432
#define F_V0  36864    // V buf: hi 64x144, lo at +9216 (18432 per buf)
#define F_V1  55296
#define F_M0  73728    // mask buf: 128x72 = 9216
#define F_M1  82944
#define F_BYTES 92160

__global__ __launch_bounds__(256, 2) void fused_attn(float* __restrict__ attn) {
    extern __shared__ char sm[];
    const uint32_t sb = smem_u32(sm);
    const int h = blockIdx.x, q0 = blockIdx.y * 128, tid = threadIdx.x;
    const int wid = tid >> 5, lane = tid & 31;
    const int lr = lane & 15, lc = lane >> 4;
    const int lam = lane & 3, r4 = lane >> 2;

    // ---- stage Q (128x64 hi+lo) into smem [0 / 18432], load frags, free ----
    {
        const __nv_bfloat16* qh = g_qhi + ((size_t)(h * SS + q0)) * DD;
        const __nv_bfloat16* ql = g_qlo + ((size_t)(h * SS + q0)) * DD;
#pragma unroll
        for (int j = 0; j < 4; j++) {
            int i = tid + j * 256, row = i >> 3, u = i & 7;
            *(uint4*)(sm + row * 144 + u * 16) = *(const uint4*)(qh + row * DD + u * 8);
            *(uint4*)(sm + 18432 + row * 144 + u * 16) = *(const uint4*)(ql + row * DD + u * 8);
        }
    }
    __syncthreads();
    uint32_t qh_f[4][4], ql_f[4][4];
    {
        const uint32_t qa = sb + (uint32_t)(wid * 16 + lr) * 144 + lc * 16;
#pragma unroll
        for (int ks = 0; ks < 4; ks++) {
            ldsm4(qh_f[ks], qa + ks * 32);
            ldsm4(ql_f[ks], qa + 18432 + ks * 32);
        }
    }
    __syncthreads();

    // ---- prefetch tile 0 ----
    {
        const __nv_bfloat16* kh = g_khi + ((size_t)(h * SS)) * DD;
        const __nv_bfloat16* kl = g_klo + ((size_t)(h * SS)) * DD;
#pragma unroll
        for (int j = 0; j < 2; j++) {
            int i = tid + j * 256, row = i >> 3, u = i & 7;
            cp16(sb + F_K0 + row * 144 + u * 16, kh + row * DD + u * 8);
            cp16(sb + F_K0 + 9216 + row * 144 + u * 16, kl + row * DD + u * 8);
        }
#pragma unroll
        for (int j = 0; j < 2; j++) {
            int i = tid + j * 256, d = i >> 3, u = i & 7;
            size_t go = ((size_t)(h * DD + d)) * SS + u * 8;
            cp16(sb + F_V0 + d * 144 + u * 16, g_vthi + go);
            cp16(sb + F_V0 + 9216 + d * 144 + u * 16, g_vtlo + go);
        }
#pragma unroll
        for (int j = 0; j < 4; j++) {
            int i = tid + j * 256, row = i >> 3, u = i & 7;
            cp8(sb + F_M0 + row * 72 + u * 8, g_mask8 + (size_t)(q0 + row) * SS + u * 8);
        }
        CP_COMMIT();
    }

    float oacc[8][4];
#pragma unroll
    for (int n = 0; n < 8; n++)
#pragma unroll
        for (int c = 0; c < 4; c++) oacc[n][c] = 0.f;

    for (int kt = 0; kt < 64; kt++) {
        CP_WAIT(0);
        __syncthreads();
        if (kt < 63) {  // prefetch kt+1
            const int kn = (kt + 1) * 64;
            const int nb = (kt + 1) & 1;
            const uint32_t kb = sb + (nb ? F_K1 : F_K0);
            const uint32_t vb = sb + (nb ? F_V1 : F_V0);
            const uint32_t mb = sb + (nb ? F_M1 : F_M0);
            const __nv_bfloat16* kh = g_khi + ((size_t)(h * SS + kn)) * DD;
            const __nv_bfloat16* kl = g_klo + ((size_t)(h * SS + kn)) * DD;
#pragma unroll
            for (int j = 0; j < 2; j++) {
                int i = tid + j * 256, row = i >> 3, u = i & 7;
                cp16(kb + row * 144 + u * 16, kh + row * DD + u * 8);
                cp16(kb + 9216 + row * 144 + u * 16, kl + row * DD + u * 8);
            }
#pragma unroll
            for (int j = 0; j < 2; j++) {
                int i = tid + j * 256, d = i >> 3, u = i & 7;
                size_t go = ((size_t)(h * DD + d)) * SS + kn + u * 8;
                cp16(vb + d * 144 + u * 16, g_vthi + go);
                cp16(vb + 9216 + d * 144 + u * 16, g_vtlo + go);
            }
#pragma unroll
            for (int j = 0; j < 4; j++) {
                int i = tid + j * 256, row = i >> 3, u = i & 7;
                cp8(mb + row * 72 + u * 8,
                    g_mask8 + (size_t)(q0 + row) * SS + kn + u * 8);
            }
            CP_COMMIT();
        }
        const uint32_t kbase = sb + ((kt & 1) ? F_K1 : F_K0);
        const uint32_t vbase = sb + ((kt & 1) ? F_V1 : F_V0);
        const char* mbase = sm + ((kt & 1) ? F_M1 : F_M0);
        const int k0 = kt * 64;

        // ---- QK^T: warp tile 16q x 64k ----
        float acc[8][4];
#pragma unroll
        for (int n = 0; n < 8; n++)
#pragma unroll
            for (int c = 0; c < 4; c++) acc[n][c] = 0.f;
#pragma unroll
        for (int ks = 0; ks < 4; ks++) {
#pragma unroll
            for (int cg = 0; cg < 4; cg++) {
                uint32_t bh[4], bl[4];
                const uint32_t kadr = kbase + (uint32_t)(cg * 16 + lr) * 144 + lc * 16 + ks * 32;
                ldsm4(bh, kadr);
                ldsm4(bl, kadr + 9216);
                mma16816(acc[2 * cg], qh_f[ks], bh[0], bh[2]);
                mma16816(acc[2 * cg + 1], qh_f[ks], bh[1], bh[3]);
                mma16816(acc[2 * cg], qh_f[ks], bl[0], bl[2]);
                mma16816(acc[2 * cg + 1], qh_f[ks], bl[1], bl[3]);
                mma16816(acc[2 * cg], ql_f[ks], bh[0], bh[2]);
                mma16816(acc[2 * cg + 1], ql_f[ks], bh[1], bh[3]);
            }
        }

        // ---- epilogue: mask -> exp -> attn STG -> reg A-frags -> PV ----
        const int rowl = wid * 16 + r4;
        float sA = 0.f, sB = 0.f;
#pragma unroll
        for (int cg = 0; cg < 4; cg++) {
            const int cb = cg * 16 + lam * 2;
            uchar2 mA0 = *(const uchar2*)(mbase + rowl * 72 + cb);
            uchar2 mA8 = *(const uchar2*)(mbase + rowl * 72 + cb + 8);
            uchar2 mB0 = *(const uchar2*)(mbase + (rowl + 8) * 72 + cb);
            uchar2 mB8 = *(const uchar2*)(mbase + (rowl + 8) * 72 + cb + 8);
            float eA0 = mA0.x ? 0.f : __expf(acc[2 * cg][0]);
            float eA1 = mA0.y ? 0.f : __expf(acc[2 * cg][1]);
            float eB0 = mB0.x ? 0.f : __expf(acc[2 * cg][2]);
            float eB1 = mB0.y ? 0.f : __expf(acc[2 * cg][3]);
            float eA8 = mA8.x ? 0.f : __expf(acc[2 * cg + 1][0]);
            float eA9 = mA8.y ? 0.f : __expf(acc[2 * cg + 1][1]);
            float eB8 = mB8.x ? 0.f : __expf(acc[2 * cg + 1][2]);
            float eB9 = mB8.y ? 0.f : __expf(acc[2 * cg + 1][3]);
            sA += (eA0 + eA1) + (eA8 + eA9);
            sB += (eB0 + eB1) + (eB8 + eB9);
            size_t base = ((size_t)(h * SS + q0 + rowl)) * SS + k0 + cb;
            *(float2*)(attn + base) = make_float2(eA0, eA1);
            *(float2*)(attn + base + 8) = make_float2(eA8, eA9);
            *(float2*)(attn + base + 8 * SS) = make_float2(eB0, eB1);
            *(float2*)(attn + base + 8 * SS + 8) = make_float2(eB8, eB9);
            float rA0, rA1, rB0, rB1, rA8, rA9, rB8, rB9;
            uint32_t pah[4], pal[4];
            pah[0] = packhi2(eA0, eA1, &rA0, &rA1);
            pah[1] = packhi2(eB0, eB1, &rB0, &rB1);
            pah[2] = packhi2(eA8, eA9, &rA8, &rA9);
            pah[3] = packhi2(eB8, eB9, &rB8, &rB9);
            pal[0] = packlo2(rA0, rA1);
            pal[1] = packlo2(rB0, rB1);
            pal[2] = packlo2(rA8, rA9);
            pal[3] = packlo2(rB8, rB9);
#pragma unroll
            for (int ng = 0; ng < 4; ng++) {
                uint32_t vh[4], vl[4];
                const uint32_t vadr = vbase + (uint32_t)(ng * 16 + lr) * 144 + lc * 16 + cg * 32;
                ldsm4(vh, vadr);
                ldsm4(vl, vadr + 9216);
                mma16816(oacc[2 * ng], pah, vh[0], vh[2]);
                mma16816(oacc[2 * ng + 1], pah, vh[1], vh[3]);
                mma16816(oacc[2 * ng], pah, vl[0], vl[2]);
                mma16816(oacc[2 * ng + 1], pah, vl[1], vl[3]);
                mma16816(oacc[2 * ng], pal, vh[0], vh[2]);
                mma16816(oacc[2 * ng + 1], pal, vh[1], vh[3]);
            }
        }
        sA += __shfl_xor_sync(~0u, sA, 1); sA += __shfl_xor_sync(~0u, sA, 2);
        sB += __shfl_xor_sync(~0u, sB, 1); sB += __shfl_xor_sync(~0u, sB, 2);
        if (lam == 0) {
            size_t so = ((size_t)(h * 64 + kt)) * SS + q0;
            g_se[so + rowl] = sA;
            g_se[so + rowl + 8] = sB;
        }
    }
    // ---- write unnormalized out ----
    const int rowl = wid * 16 + r4;
#pragma unroll
    for (int nb = 0; nb < 8; nb++) {
        int col = nb * 8 + lam * 2;
        float* op = g_outun + ((size_t)(h * SS + q0 + rowl)) * DD + col;
        *(float2*)op = make_float2(oacc[nb][0], oacc[nb][1]);
        *(float2*)(op + 8 * DD) = make_float2(oacc[nb][2], oacc[nb][3]);
    }
}

// ===================== row inverse sums =====================
__global__ __launch_bounds__(256) void rowinv_kernel() {
    int idx = blockIdx.x * 256 + threadIdx.x;
    int h = idx >> 12, row = idx & 4095;
    float s = 0.f;
#pragma unroll 8
    for (int t = 0; t < 64; t++) s += g_se[((size_t)(h * 64 + t)) * SS + row];
    g_rowinv[idx] = 1.0f / s;
}

// ===================== normalize attn (stream) =====================
__global__ __launch_bounds__(256) void norm_attn(float* __restrict__ attn) {
    const int idx = blockIdx.x;
    const float ri = g_rowinv[idx];
    float4* p = (float4*)(attn + (size_t)idx * SS);
    const int tid = threadIdx.x;
#pragma unroll
    for (int i = 0; i < 4; i++) {
        float4 v = p[tid + i * 256];
        v.x *= ri; v.y *= ri; v.z *= ri; v.w *= ri;
        p[tid + i * 256] = v;
    }
}

// ===================== normalize out =====================
__global__ __launch_bounds__(256) void norm_out(float* __restrict__ out) {
    int i = blockIdx.x * 256 + threadIdx.x;
    out[i] = g_outun[i] * g_rowinv[i >> 6];
}

// ===================== launch =====================
extern "C" void kernel_launch(void* const* d_in, const int* in_sizes, int n_in,
                              void* d_out, int out_size) {
    const float* q = (const float*)d_in[0];
    const float* k = (const float*)d_in[1];
    const float* v = (const float*)d_in[2];
    const int* mask = (const int*)d_in[3];
    float* out = (float*)d_out;
    float* attn = out + (size_t)HH * SS * DD;

    cudaFuncSetAttribute(fused_attn, cudaFuncAttributeMaxDynamicSharedMemorySize, F_BYTES);

    convert_qk<<<(HH * SS * DD) / 256, 256>>>(q, k);
    convert_v<<<dim3(SS / 64, HH), 256>>>(v);
    convert_mask<<<(SS * SS) / 1024, 256>>>(mask);
    fused_attn<<<dim3(HH, SS / 128), 256, F_BYTES>>>(attn);
    rowinv_kernel<<<HH * SS / 256, 256>>>();
    norm_attn<<<HH * SS, 256>>>(attn);
    norm_out<<<HH * SS * DD / 256, 256>>>(out);
}

// round 14
// speedup vs baseline: 1.3889x; 1.3086x over previous
#include <cuda_runtime.h>
#include <cuda_bf16.h>
#include <cuda_fp16.h>
#include <stdint.h>

#define HH 16
#define SS 4096
#define DD 64
#define QSCALE 0.180336884f   // 0.125 * log2(e)

__device__ __align__(16) __nv_bfloat16 g_qhi[HH * SS * DD];
__device__ __align__(16) __nv_bfloat16 g_qlo[HH * SS * DD];
__device__ __align__(16) __nv_bfloat16 g_khi[HH * SS * DD];
__device__ __align__(16) __nv_bfloat16 g_klo[HH * SS * DD];
__device__ __align__(16) __half g_vt[HH * DD * SS];     // fp16, transposed [h][d][s]
__device__ __align__(16) unsigned char g_mask8[(size_t)SS * SS];
__device__ float g_rowinv[HH * SS];

static __device__ __forceinline__ uint32_t smem_u32(const void* p) {
    uint32_t a;
    asm("{ .reg .u64 t; cvta.to.shared.u64 t, %1; cvt.u32.u64 %0, t; }" : "=r"(a) : "l"(p));
    return a;
}
static __device__ __forceinline__ void ldsm4(uint32_t* r, uint32_t a) {
    asm volatile("ldmatrix.sync.aligned.m8n8.x4.shared.b16 {%0,%1,%2,%3}, [%4];"
        : "=r"(r[0]), "=r"(r[1]), "=r"(r[2]), "=r"(r[3]) : "r"(a));
}
static __device__ __forceinline__ void mma_bf16(float* c, const uint32_t* a,
                                                uint32_t b0, uint32_t b1) {
    asm volatile("mma.sync.aligned.m16n8k16.row.col.f32.bf16.bf16.f32 "
        "{%0,%1,%2,%3}, {%4,%5,%6,%7}, {%8,%9}, {%0,%1,%2,%3};"
        : "+f"(c[0]), "+f"(c[1]), "+f"(c[2]), "+f"(c[3])
        : "r"(a[0]), "r"(a[1]), "r"(a[2]), "r"(a[3]), "r"(b0), "r"(b1));
}
static __device__ __forceinline__ void mma_f16(float* c, const uint32_t* a,
                                               uint32_t b0, uint32_t b1) {
    asm volatile("mma.sync.aligned.m16n8k16.row.col.f32.f16.f16.f32 "
        "{%0,%1,%2,%3}, {%4,%5,%6,%7}, {%8,%9}, {%0,%1,%2,%3};"
        : "+f"(c[0]), "+f"(c[1]), "+f"(c[2]), "+f"(c[3])
        : "r"(a[0]), "r"(a[1]), "r"(a[2]), "r"(a[3]), "r"(b0), "r"(b1));
}
static __device__ __forceinline__ void cp16(uint32_t s, const void* g) {
    asm volatile("cp.async.cg.shared.global [%0], [%1], 16;" :: "r"(s), "l"(g));
}
static __device__ __forceinline__ void cp8(uint32_t s, const void* g) {
    asm volatile("cp.async.ca.shared.global [%0], [%1], 8;" :: "r"(s), "l"(g));
}
#define CP_COMMIT() asm volatile("cp.async.commit_group;" ::: "memory")
#define CP_WAIT(n)  asm volatile("cp.async.wait_group %0;" :: "n"(n) : "memory")

static __device__ __forceinline__ float ex2(float x) {
    float r;
    asm("ex2.approx.f32 %0, %1;" : "=f"(r) : "f"(x));
    return r;
}
// pack (lo=a, hi=b) as fp16x2
static __device__ __forceinline__ uint32_t packf16(float a, float b) {
    uint32_t r;
    asm("cvt.rn.f16x2.f32 %0, %1, %2;" : "=r"(r) : "f"(b), "f"(a));
    return r;
}

// ===================== converts =====================
__global__ __launch_bounds__(256) void convert_qk(const float* __restrict__ q,
                                                  const float* __restrict__ k) {
    int i = blockIdx.x * 256 + threadIdx.x;
    float fq = q[i] * QSCALE;                 // fold softmax scale + log2e
    __nv_bfloat16 qh = __float2bfloat16(fq);
    g_qhi[i] = qh; g_qlo[i] = __float2bfloat16(fq - __bfloat162float(qh));
    float fk = k[i];
    __nv_bfloat16 kh = __float2bfloat16(fk);
    g_khi[i] = kh; g_klo[i] = __float2bfloat16(fk - __bfloat162float(kh));
}
__global__ __launch_bounds__(256) void convert_v(const float* __restrict__ v) {
    __shared__ __half tv[64][65];
    const int h = blockIdx.y, s0 = blockIdx.x * 64, tid = threadIdx.x;
#pragma unroll
    for (int j = 0; j < 16; j++) {
        int i = tid + j * 256, sr = i >> 6, d = i & 63;
        tv[sr][d] = __float2half(v[((size_t)(h * SS + s0 + sr)) * DD + d]);
    }
    __syncthreads();
#pragma unroll
    for (int j = 0; j < 16; j++) {
        int i = tid + j * 256, d = i >> 6, sr = i & 63;
        g_vt[((size_t)(h * DD + d)) * SS + s0 + sr] = tv[sr][d];
    }
}
__global__ __launch_bounds__(256) void convert_mask(const int* __restrict__ m) {
    size_t i = ((size_t)blockIdx.x * 256 + threadIdx.x) * 4;
    int4 v = *(const int4*)(m + i);
    uchar4 b;
    b.x = v.x ? 1 : 0; b.y = v.y ? 1 : 0; b.z = v.z ? 1 : 0; b.w = v.w ? 1 : 0;
    *(uchar4*)(g_mask8 + i) = b;
}

// ===================== fused kernel smem (73.7KB -> 2 blocks/SM) ============
#define F_K0  0        // K buf: hi 64x144 = 9216, lo at +9216 (18432/buf)
#define F_K1  18432
#define F_V0  36864    // V buf: fp16 64x144 (9216/buf)
#define F_V1  46080
#define F_M0  55296    // mask buf: 128x72 (9216/buf)
#define F_M1  64512
#define F_BYTES 73728

__global__ __launch_bounds__(256, 2) void fused_attn(float* __restrict__ attn,
                                                     float* __restrict__ out) {
    extern __shared__ char sm[];
    const uint32_t sb = smem_u32(sm);
    const int h = blockIdx.x, q0 = blockIdx.y * 128, tid = threadIdx.x;
    const int wid = tid >> 5, lane = tid & 31;
    const int lr = lane & 15, lc = lane >> 4;
    const int lam = lane & 3, r4 = lane >> 2;

    // ---- stage Q into smem, load frags into registers, then free smem ----
    {
        const __nv_bfloat16* qh = g_qhi + ((size_t)(h * SS + q0)) * DD;
        const __nv_bfloat16* ql = g_qlo + ((size_t)(h * SS + q0)) * DD;
#pragma unroll
        for (int j = 0; j < 4; j++) {
            int i = tid + j * 256, row = i >> 3, u = i & 7;
            *(uint4*)(sm + row * 144 + u * 16) = *(const uint4*)(qh + row * DD + u * 8);
            *(uint4*)(sm + 18432 + row * 144 + u * 16) = *(const uint4*)(ql + row * DD + u * 8);
        }
    }
    __syncthreads();
    uint32_t qh_f[4][4], ql_f[4][4];
    {
        const uint32_t qa = sb + (uint32_t)(wid * 16 + lr) * 144 + lc * 16;
#pragma unroll
        for (int ks = 0; ks < 4; ks++) {
            ldsm4(qh_f[ks], qa + ks * 32);
            ldsm4(ql_f[ks], qa + 18432 + ks * 32);
        }
    }
    __syncthreads();

    // ---- prefetch tile 0 ----
    {
        const __nv_bfloat16* kh = g_khi + ((size_t)(h * SS)) * DD;
        const __nv_bfloat16* kl = g_klo + ((size_t)(h * SS)) * DD;
#pragma unroll
        for (int j = 0; j < 2; j++) {
            int i = tid + j * 256, row = i >> 3, u = i & 7;
            cp16(sb + F_K0 + row * 144 + u * 16, kh + row * DD + u * 8);
            cp16(sb + F_K0 + 9216 + row * 144 + u * 16, kl + row * DD + u * 8);
        }
        {
            int d = tid >> 2, u = tid & 3;   // 256 threads: 64 d x 4 u(16B each)
            cp16(sb + F_V0 + d * 144 + u * 32,
                 g_vt + ((size_t)(h * DD + d)) * SS + u * 16);
            cp16(sb + F_V0 + d * 144 + u * 32 + 16,
                 g_vt + ((size_t)(h * DD + d)) * SS + u * 16 + 8);
        }
#pragma unroll
        for (int j = 0; j < 4; j++) {
            int i = tid + j * 256, row = i >> 3, u = i & 7;
            cp8(sb + F_M0 + row * 72 + u * 8, g_mask8 + (size_t)(q0 + row) * SS + u * 8);
        }
        CP_COMMIT();
    }

    float oacc[8][4];
#pragma unroll
    for (int n = 0; n < 8; n++)
#pragma unroll
        for (int c = 0; c < 4; c++) oacc[n][c] = 0.f;
    float sA = 0.f, sB = 0.f;   // full-row exp sums, accumulated across kt

    for (int kt = 0; kt < 64; kt++) {
        CP_WAIT(0);
        __syncthreads();
        if (kt < 63) {  // prefetch kt+1
            const int kn = (kt + 1) * 64;
            const int nb = (kt + 1) & 1;
            const uint32_t kb = sb + (nb ? F_K1 : F_K0);
            const uint32_t vb = sb + (nb ? F_V1 : F_V0);
            const uint32_t mb = sb + (nb ? F_M1 : F_M0);
            const __nv_bfloat16* kh = g_khi + ((size_t)(h * SS + kn)) * DD;
            const __nv_bfloat16* kl = g_klo + ((size_t)(h * SS + kn)) * DD;
#pragma unroll
            for (int j = 0; j < 2; j++) {
                int i = tid + j * 256, row = i >> 3, u = i & 7;
                cp16(kb + row * 144 + u * 16, kh + row * DD + u * 8);
                cp16(kb + 9216 + row * 144 + u * 16, kl + row * DD + u * 8);
            }
            {
                int d = tid >> 2, u = tid & 3;
                cp16(vb + d * 144 + u * 32,
                     g_vt + ((size_t)(h * DD + d)) * SS + kn + u * 16);
                cp16(vb + d * 144 + u * 32 + 16,
                     g_vt + ((size_t)(h * DD + d)) * SS + kn + u * 16 + 8);
            }
#pragma unroll
            for (int j = 0; j < 4; j++) {
                int i = tid + j * 256, row = i >> 3, u = i & 7;
                cp8(mb + row * 72 + u * 8,
                    g_mask8 + (size_t)(q0 + row) * SS + kn + u * 8);
            }
            CP_COMMIT();
        }
        const uint32_t kbase = sb + ((kt & 1) ? F_K1 : F_K0);
        const uint32_t vbase = sb + ((kt & 1) ? F_V1 : F_V0);
        const char* mbase = sm + ((kt & 1) ? F_M1 : F_M0);
        const int k0 = kt * 64;

        // ---- QK^T (bf16 3-product): warp tile 16q x 64k ----
        float acc[8][4];
#pragma unroll
        for (int n = 0; n < 8; n++)
#pragma unroll
            for (int c = 0; c < 4; c++) acc[n][c] = 0.f;
#pragma unroll
        for (int ks = 0; ks < 4; ks++) {
#pragma unroll
            for (int cg = 0; cg < 4; cg++) {
                uint32_t bh[4], bl[4];
                const uint32_t kadr = kbase + (uint32_t)(cg * 16 + lr) * 144 + lc * 16 + ks * 32;
                ldsm4(bh, kadr);
                ldsm4(bl, kadr + 9216);
                mma_bf16(acc[2 * cg], qh_f[ks], bh[0], bh[2]);
                mma_bf16(acc[2 * cg + 1], qh_f[ks], bh[1], bh[3]);
                mma_bf16(acc[2 * cg], qh_f[ks], bl[0], bl[2]);
                mma_bf16(acc[2 * cg + 1], qh_f[ks], bl[1], bl[3]);
                mma_bf16(acc[2 * cg], ql_f[ks], bh[0], bh[2]);
                mma_bf16(acc[2 * cg + 1], ql_f[ks], bh[1], bh[3]);
            }
        }

        // ---- epilogue: mask -> ex2 -> attn STG -> fp16 A-frags -> PV ----
        const int rowl = wid * 16 + r4;
#pragma unroll
        for (int cg = 0; cg < 4; cg++) {
            const int cb = cg * 16 + lam * 2;
            uchar2 mA0 = *(const uchar2*)(mbase + rowl * 72 + cb);
            uchar2 mA8 = *(const uchar2*)(mbase + rowl * 72 + cb + 8);
            uchar2 mB0 = *(const uchar2*)(mbase + (rowl + 8) * 72 + cb);
            uchar2 mB8 = *(const uchar2*)(mbase + (rowl + 8) * 72 + cb + 8);
            float eA0 = mA0.x ? 0.f : ex2(acc[2 * cg][0]);
            float eA1 = mA0.y ? 0.f : ex2(acc[2 * cg][1]);
            float eB0 = mB0.x ? 0.f : ex2(acc[2 * cg][2]);
            float eB1 = mB0.y ? 0.f : ex2(acc[2 * cg][3]);
            float eA8 = mA8.x ? 0.f : ex2(acc[2 * cg + 1][0]);
            float eA9 = mA8.y ? 0.f : ex2(acc[2 * cg + 1][1]);
            float eB8 = mB8.x ? 0.f : ex2(acc[2 * cg + 1][2]);
            float eB9 = mB8.y ? 0.f : ex2(acc[2 * cg + 1][3]);
            sA += (eA0 + eA1) + (eA8 + eA9);
            sB += (eB0 + eB1) + (eB8 + eB9);
            size_t base = ((size_t)(h * SS + q0 + rowl)) * SS + k0 + cb;
            *(float2*)(attn + base) = make_float2(eA0, eA1);
            *(float2*)(attn + base + 8) = make_float2(eA8, eA9);
            *(float2*)(attn + base + 8 * SS) = make_float2(eB0, eB1);
            *(float2*)(attn + base + 8 * SS + 8) = make_float2(eB8, eB9);
            uint32_t pa[4];
            pa[0] = packf16(eA0, eA1);
            pa[1] = packf16(eB0, eB1);
            pa[2] = packf16(eA8, eA9);
            pa[3] = packf16(eB8, eB9);
#pragma unroll
            for (int ng = 0; ng < 4; ng++) {
                uint32_t vh[4];
                ldsm4(vh, vbase + (uint32_t)(ng * 16 + lr) * 144 + lc * 16 + cg * 32);
                mma_f16(oacc[2 * ng], pa, vh[0], vh[2]);
                mma_f16(oacc[2 * ng + 1], pa, vh[1], vh[3]);
            }
        }
    }
    // ---- finalize: row sums -> rowinv + normalized out ----
    sA += __shfl_xor_sync(~0u, sA, 1); sA += __shfl_xor_sync(~0u, sA, 2);
    sB += __shfl_xor_sync(~0u, sB, 1); sB += __shfl_xor_sync(~0u, sB, 2);
    const float invA = 1.0f / sA, invB = 1.0f / sB;
    const int rowl = wid * 16 + r4;
    if (lam == 0) {
        g_rowinv[h * SS + q0 + rowl] = invA;
        g_rowinv[h * SS + q0 + rowl + 8] = invB;
    }
#pragma unroll
    for (int nb = 0; nb < 8; nb++) {
        int col = nb * 8 + lam * 2;
        float* op = out + ((size_t)(h * SS + q0 + rowl)) * DD + col;
        *(float2*)op = make_float2(oacc[nb][0] * invA, oacc[nb][1] * invA);
        *(float2*)(op + 8 * DD) = make_float2(oacc[nb][2] * invB, oacc[nb][3] * invB);
    }
}

// ===================== normalize attn (stream) =====================
__global__ __launch_bounds__(256) void norm_attn(float* __restrict__ attn) {
    const int idx = blockIdx.x;
    const float ri = g_rowinv[idx];
    float4* p = (float4*)(attn + (size_t)idx * SS);
    const int tid = threadIdx.x;
#pragma unroll
    for (int i = 0; i < 4; i++) {
        float4 v = p[tid + i * 256];
        v.x *= ri; v.y *= ri; v.z *= ri; v.w *= ri;
        p[tid + i * 256] = v;
    }
}

// ===================== launch =====================
extern "C" void kernel_launch(void* const* d_in, const int* in_sizes, int n_in,
                              void* d_out, int out_size) {
    const float* q = (const float*)d_in[0];
    const float* k = (const float*)d_in[1];
    const float* v = (const float*)d_in[2];
    const int* mask = (const int*)d_in[3];
    float* out = (float*)d_out;
    float* attn = out + (size_t)HH * SS * DD;

    cudaFuncSetAttribute(fused_attn, cudaFuncAttributeMaxDynamicSharedMemorySize, F_BYTES);

    convert_qk<<<(HH * SS * DD) / 256, 256>>>(q, k);
    convert_v<<<dim3(SS / 64, HH), 256>>>(v);
    convert_mask<<<(SS * SS) / 1024, 256>>>(mask);
    fused_attn<<<dim3(HH, SS / 128), 256, F_BYTES>>>(attn, out);
    norm_attn<<<HH * SS, 256>>>(attn);
}

// round 15
// speedup vs baseline: 1.5774x; 1.1357x over previous
#include <cuda_runtime.h>
#include <cuda_fp16.h>
#include <stdint.h>

#define HH 16
#define SS 4096
#define DD 64
#define QSCALE 0.180336884f   // 0.125 * log2(e)

__device__ __align__(16) __half g_qhi[HH * SS * DD];
__device__ __align__(16) __half g_qlo[HH * SS * DD];
__device__ __align__(16) __half g_k[HH * SS * DD];
__device__ __align__(16) __half g_vt[HH * DD * SS];     // fp16, transposed [h][d][s]
__device__ __align__(16) unsigned char g_mask8[(size_t)SS * SS];
__device__ float g_rowinv[HH * SS];

static __device__ __forceinline__ uint32_t smem_u32(const void* p) {
    uint32_t a;
    asm("{ .reg .u64 t; cvta.to.shared.u64 t, %1; cvt.u32.u64 %0, t; }" : "=r"(a) : "l"(p));
    return a;
}
static __device__ __forceinline__ void ldsm4(uint32_t* r, uint32_t a) {
    asm volatile("ldmatrix.sync.aligned.m8n8.x4.shared.b16 {%0,%1,%2,%3}, [%4];"
        : "=r"(r[0]), "=r"(r[1]), "=r"(r[2]), "=r"(r[3]) : "r"(a));
}
static __device__ __forceinline__ void mma_f16(float* c, const uint32_t* a,
                                               uint32_t b0, uint32_t b1) {
    asm volatile("mma.sync.aligned.m16n8k16.row.col.f32.f16.f16.f32 "
        "{%0,%1,%2,%3}, {%4,%5,%6,%7}, {%8,%9}, {%0,%1,%2,%3};"
        : "+f"(c[0]), "+f"(c[1]), "+f"(c[2]), "+f"(c[3])
        : "r"(a[0]), "r"(a[1]), "r"(a[2]), "r"(a[3]), "r"(b0), "r"(b1));
}
static __device__ __forceinline__ void cp16(uint32_t s, const void* g) {
    asm volatile("cp.async.cg.shared.global [%0], [%1], 16;" :: "r"(s), "l"(g));
}
static __device__ __forceinline__ void cp8(uint32_t s, const void* g) {
    asm volatile("cp.async.ca.shared.global [%0], [%1], 8;" :: "r"(s), "l"(g));
}
#define CP_COMMIT() asm volatile("cp.async.commit_group;" ::: "memory")
#define CP_WAIT(n)  asm volatile("cp.async.wait_group %0;" :: "n"(n) : "memory")

static __device__ __forceinline__ float ex2(float x) {
    float r;
    asm("ex2.approx.f32 %0, %1;" : "=f"(r) : "f"(x));
    return r;
}
static __device__ __forceinline__ uint32_t packf16(float a, float b) {
    uint32_t r;
    asm("cvt.rn.f16x2.f32 %0, %1, %2;" : "=r"(r) : "f"(b), "f"(a));
    return r;
}

// ===================== converts =====================
__global__ __launch_bounds__(256) void convert_qk(const float* __restrict__ q,
                                                  const float* __restrict__ k) {
    int i = blockIdx.x * 256 + threadIdx.x;
    float fq = q[i] * QSCALE;                 // fold softmax scale + log2e
    __half qh = __float2half(fq);
    g_qhi[i] = qh;
    g_qlo[i] = __float2half(fq - __half2float(qh));
    g_k[i] = __float2half(k[i]);
}
__global__ __launch_bounds__(256) void convert_v(const float* __restrict__ v) {
    __shared__ __half tv[64][65];
    const int h = blockIdx.y, s0 = blockIdx.x * 64, tid = threadIdx.x;
#pragma unroll
    for (int j = 0; j < 16; j++) {
        int i = tid + j * 256, sr = i >> 6, d = i & 63;
        tv[sr][d] = __float2half(v[((size_t)(h * SS + s0 + sr)) * DD + d]);
    }
    __syncthreads();
#pragma unroll
    for (int j = 0; j < 16; j++) {
        int i = tid + j * 256, d = i >> 6, sr = i & 63;
        g_vt[((size_t)(h * DD + d)) * SS + s0 + sr] = tv[sr][d];
    }
}
__global__ __launch_bounds__(256) void convert_mask(const int* __restrict__ m) {
    size_t i = ((size_t)blockIdx.x * 256 + threadIdx.x) * 4;
    int4 v = *(const int4*)(m + i);
    uchar4 b;
    b.x = v.x ? 1 : 0; b.y = v.y ? 1 : 0; b.z = v.z ? 1 : 0; b.w = v.w ? 1 : 0;
    *(uchar4*)(g_mask8 + i) = b;
}

// ===================== fused kernel smem (55.3KB -> 2 blocks/SM) ============
#define F_K0  0        // K buf: fp16 64x144 (9216/buf)
#define F_K1  9216
#define F_V0  18432    // V buf: fp16 64x144 (9216/buf)
#define F_V1  27648
#define F_M0  36864    // mask buf: 128x72 (9216/buf)
#define F_M1  46080
#define F_BYTES 55296

__global__ __launch_bounds__(256, 2) void fused_attn(float* __restrict__ attn,
                                                     float* __restrict__ out) {
    extern __shared__ char sm[];
    const uint32_t sb = smem_u32(sm);
    const int h = blockIdx.x, q0 = blockIdx.y * 128, tid = threadIdx.x;
    const int wid = tid >> 5, lane = tid & 31;
    const int lr = lane & 15, lc = lane >> 4;
    const int lam = lane & 3, r4 = lane >> 2;

    // ---- stage Q into smem, load frags into registers, then free smem ----
    {
        const __half* qh = g_qhi + ((size_t)(h * SS + q0)) * DD;
        const __half* ql = g_qlo + ((size_t)(h * SS + q0)) * DD;
#pragma unroll
        for (int j = 0; j < 4; j++) {
            int i = tid + j * 256, row = i >> 3, u = i & 7;
            *(uint4*)(sm + row * 144 + u * 16) = *(const uint4*)(qh + row * DD + u * 8);
            *(uint4*)(sm + 18432 + row * 144 + u * 16) = *(const uint4*)(ql + row * DD + u * 8);
        }
    }
    __syncthreads();
    uint32_t qh_f[4][4], ql_f[4][4];
    {
        const uint32_t qa = sb + (uint32_t)(wid * 16 + lr) * 144 + lc * 16;
#pragma unroll
        for (int ks = 0; ks < 4; ks++) {
            ldsm4(qh_f[ks], qa + ks * 32);
            ldsm4(ql_f[ks], qa + 18432 + ks * 32);
        }
    }
    __syncthreads();

    // ---- prefetch tile 0 ----
    {
        const __half* kk = g_k + ((size_t)(h * SS)) * DD;
        {
            int i = tid, row = i >> 1, u = i & 1;   // 256 thr: 128 rows? no: 64 rows x 4x16B
            // K: 64 rows x 128B; 512 cp16 needed -> 2 per thread
            int r0 = tid >> 2, u4 = tid & 3;
            cp16(sb + F_K0 + r0 * 144 + u4 * 32, kk + r0 * DD + u4 * 16);
            cp16(sb + F_K0 + r0 * 144 + u4 * 32 + 16, kk + r0 * DD + u4 * 16 + 8);
            (void)row; (void)u; (void)i;
        }
        {
            int d = tid >> 2, u = tid & 3;
            cp16(sb + F_V0 + d * 144 + u * 32,
                 g_vt + ((size_t)(h * DD + d)) * SS + u * 16);
            cp16(sb + F_V0 + d * 144 + u * 32 + 16,
                 g_vt + ((size_t)(h * DD + d)) * SS + u * 16 + 8);
        }
#pragma unroll
        for (int j = 0; j < 4; j++) {
            int i = tid + j * 256, row = i >> 3, u = i & 7;
            cp8(sb + F_M0 + row * 72 + u * 8, g_mask8 + (size_t)(q0 + row) * SS + u * 8);
        }
        CP_COMMIT();
    }

    float oacc[8][4];
#pragma unroll
    for (int n = 0; n < 8; n++)
#pragma unroll
        for (int c = 0; c < 4; c++) oacc[n][c] = 0.f;
    float sA = 0.f, sB = 0.f;

    for (int kt = 0; kt < 64; kt++) {
        CP_WAIT(0);
        __syncthreads();
        if (kt < 63) {  // prefetch kt+1
            const int kn = (kt + 1) * 64;
            const int nb = (kt + 1) & 1;
            const uint32_t kb = sb + (nb ? F_K1 : F_K0);
            const uint32_t vb = sb + (nb ? F_V1 : F_V0);
            const uint32_t mb = sb + (nb ? F_M1 : F_M0);
            const __half* kk = g_k + ((size_t)(h * SS + kn)) * DD;
            {
                int r0 = tid >> 2, u4 = tid & 3;
                cp16(kb + r0 * 144 + u4 * 32, kk + r0 * DD + u4 * 16);
                cp16(kb + r0 * 144 + u4 * 32 + 16, kk + r0 * DD + u4 * 16 + 8);
            }
            {
                int d = tid >> 2, u = tid & 3;
                cp16(vb + d * 144 + u * 32,
                     g_vt + ((size_t)(h * DD + d)) * SS + kn + u * 16);
                cp16(vb + d * 144 + u * 32 + 16,
                     g_vt + ((size_t)(h * DD + d)) * SS + kn + u * 16 + 8);
            }
#pragma unroll
            for (int j = 0; j < 4; j++) {
                int i = tid + j * 256, row = i >> 3, u = i & 7;
                cp8(mb + row * 72 + u * 8,
                    g_mask8 + (size_t)(q0 + row) * SS + kn + u * 8);
            }
            CP_COMMIT();
        }
        const uint32_t kbase = sb + ((kt & 1) ? F_K1 : F_K0);
        const uint32_t vbase = sb + ((kt & 1) ? F_V1 : F_V0);
        const char* mbase = sm + ((kt & 1) ? F_M1 : F_M0);
        const int k0 = kt * 64;

        // ---- QK^T (fp16 2-product): warp tile 16q x 64k ----
        float acc[8][4];
#pragma unroll
        for (int n = 0; n < 8; n++)
#pragma unroll
            for (int c = 0; c < 4; c++) acc[n][c] = 0.f;
#pragma unroll
        for (int ks = 0; ks < 4; ks++) {
#pragma unroll
            for (int cg = 0; cg < 4; cg++) {
                uint32_t bk[4];
                ldsm4(bk, kbase + (uint32_t)(cg * 16 + lr) * 144 + lc * 16 + ks * 32);
                mma_f16(acc[2 * cg], qh_f[ks], bk[0], bk[2]);
                mma_f16(acc[2 * cg + 1], qh_f[ks], bk[1], bk[3]);
                mma_f16(acc[2 * cg], ql_f[ks], bk[0], bk[2]);
                mma_f16(acc[2 * cg + 1], ql_f[ks], bk[1], bk[3]);
            }
        }

        // ---- epilogue: mask -> ex2 -> attn STG -> fp16 A-frags -> PV ----
        const int rowl = wid * 16 + r4;
#pragma unroll
        for (int cg = 0; cg < 4; cg++) {
            const int cb = cg * 16 + lam * 2;
            uchar2 mA0 = *(const uchar2*)(mbase + rowl * 72 + cb);
            uchar2 mA8 = *(const uchar2*)(mbase + rowl * 72 + cb + 8);
            uchar2 mB0 = *(const uchar2*)(mbase + (rowl + 8) * 72 + cb);
            uchar2 mB8 = *(const uchar2*)(mbase + (rowl + 8) * 72 + cb + 8);
            float eA0 = mA0.x ? 0.f : ex2(acc[2 * cg][0]);
            float eA1 = mA0.y ? 0.f : ex2(acc[2 * cg][1]);
            float eB0 = mB0.x ? 0.f : ex2(acc[2 * cg][2]);
            float eB1 = mB0.y ? 0.f : ex2(acc[2 * cg][3]);
            float eA8 = mA8.x ? 0.f : ex2(acc[2 * cg + 1][0]);
            float eA9 = mA8.y ? 0.f : ex2(acc[2 * cg + 1][1]);
            float eB8 = mB8.x ? 0.f : ex2(acc[2 * cg + 1][2]);
            float eB9 = mB8.y ? 0.f : ex2(acc[2 * cg + 1][3]);
            sA += (eA0 + eA1) + (eA8 + eA9);
            sB += (eB0 + eB1) + (eB8 + eB9);
            size_t base = ((size_t)(h * SS + q0 + rowl)) * SS + k0 + cb;
            *(float2*)(attn + base) = make_float2(eA0, eA1);
            *(float2*)(attn + base + 8) = make_float2(eA8, eA9);
            *(float2*)(attn + base + 8 * SS) = make_float2(eB0, eB1);
            *(float2*)(attn + base + 8 * SS + 8) = make_float2(eB8, eB9);
            uint32_t pa[4];
            pa[0] = packf16(eA0, eA1);
            pa[1] = packf16(eB0, eB1);
            pa[2] = packf16(eA8, eA9);
            pa[3] = packf16(eB8, eB9);
#pragma unroll
            for (int ng = 0; ng < 4; ng++) {
                uint32_t vh[4];
                ldsm4(vh, vbase + (uint32_t)(ng * 16 + lr) * 144 + lc * 16 + cg * 32);
                mma_f16(oacc[2 * ng], pa, vh[0], vh[2]);
                mma_f16(oacc[2 * ng + 1], pa, vh[1], vh[3]);
            }
        }
    }
    // ---- finalize: row sums -> rowinv + normalized out ----
    sA += __shfl_xor_sync(~0u, sA, 1); sA += __shfl_xor_sync(~0u, sA, 2);
    sB += __shfl_xor_sync(~0u, sB, 1); sB += __shfl_xor_sync(~0u, sB, 2);
    const float invA = 1.0f / sA, invB = 1.0f / sB;
    const int rowl = wid * 16 + r4;
    if (lam == 0) {
        g_rowinv[h * SS + q0 + rowl] = invA;
        g_rowinv[h * SS + q0 + rowl + 8] = invB;
    }
#pragma unroll
    for (int nb = 0; nb < 8; nb++) {
        int col = nb * 8 + lam * 2;
        float* op = out + ((size_t)(h * SS + q0 + rowl)) * DD + col;
        *(float2*)op = make_float2(oacc[nb][0] * invA, oacc[nb][1] * invA);
        *(float2*)(op + 8 * DD) = make_float2(oacc[nb][2] * invB, oacc[nb][3] * invB);
    }
}

// ===================== normalize attn (stream) =====================
__global__ __launch_bounds__(256) void norm_attn(float* __restrict__ attn) {
    const int idx = blockIdx.x;
    const float ri = g_rowinv[idx];
    float4* p = (float4*)(attn + (size_t)idx * SS);
    const int tid = threadIdx.x;
#pragma unroll
    for (int i = 0; i < 4; i++) {
        float4 v = p[tid + i * 256];
        v.x *= ri; v.y *= ri; v.z *= ri; v.w *= ri;
        p[tid + i * 256] = v;
    }
}

// ===================== launch =====================
extern "C" void kernel_launch(void* const* d_in, const int* in_sizes, int n_in,
                              void* d_out, int out_size) {
    const float* q = (const float*)d_in[0];
    const float* k = (const float*)d_in[1];
    const float* v = (const float*)d_in[2];
    const int* mask = (const int*)d_in[3];
    float* out = (float*)d_out;
    float* attn = out + (size_t)HH * SS * DD;

    cudaFuncSetAttribute(fused_attn, cudaFuncAttributeMaxDynamicSharedMemorySize, F_BYTES);

    convert_qk<<<(HH * SS * DD) / 256, 256>>>(q, k);
    convert_v<<<dim3(SS / 64, HH), 256>>>(v);
    convert_mask<<<(SS * SS) / 1024, 256>>>(mask);
    fused_attn<<<dim3(HH, SS / 128), 256, F_BYTES>>>(attn, out);
    norm_attn<<<HH * SS, 256>>>(attn);
}

// round 16
// speedup vs baseline: 1.6897x; 1.0712x over previous
#include <cuda_runtime.h>
#include <cuda_fp16.h>
#include <stdint.h>

#define HH 16
#define SS 4096
#define DD 64
#define QSCALE 0.180336884f   // 0.125 * log2(e)

__device__ __align__(16) __half g_qhi[HH * SS * DD];
__device__ __align__(16) __half g_qlo[HH * SS * DD];
__device__ __align__(16) __half g_k[HH * SS * DD];
__device__ __align__(16) __half g_vt[HH * DD * SS];     // fp16, transposed [h][d][s]
__device__ __align__(16) __half g_pt[(size_t)HH * SS * SS];  // fp16 unnormalized exp
__device__ __align__(16) unsigned char g_mask8[(size_t)SS * SS];
__device__ float g_rowinv[HH * SS];

static __device__ __forceinline__ uint32_t smem_u32(const void* p) {
    uint32_t a;
    asm("{ .reg .u64 t; cvta.to.shared.u64 t, %1; cvt.u32.u64 %0, t; }" : "=r"(a) : "l"(p));
    return a;
}
static __device__ __forceinline__ void ldsm4(uint32_t* r, uint32_t a) {
    asm volatile("ldmatrix.sync.aligned.m8n8.x4.shared.b16 {%0,%1,%2,%3}, [%4];"
        : "=r"(r[0]), "=r"(r[1]), "=r"(r[2]), "=r"(r[3]) : "r"(a));
}
static __device__ __forceinline__ void mma_f16(float* c, const uint32_t* a,
                                               uint32_t b0, uint32_t b1) {
    asm volatile("mma.sync.aligned.m16n8k16.row.col.f32.f16.f16.f32 "
        "{%0,%1,%2,%3}, {%4,%5,%6,%7}, {%8,%9}, {%0,%1,%2,%3};"
        : "+f"(c[0]), "+f"(c[1]), "+f"(c[2]), "+f"(c[3])
        : "r"(a[0]), "r"(a[1]), "r"(a[2]), "r"(a[3]), "r"(b0), "r"(b1));
}
static __device__ __forceinline__ void cp16(uint32_t s, const void* g) {
    asm volatile("cp.async.cg.shared.global [%0], [%1], 16;" :: "r"(s), "l"(g));
}
static __device__ __forceinline__ void cp8(uint32_t s, const void* g) {
    asm volatile("cp.async.ca.shared.global [%0], [%1], 8;" :: "r"(s), "l"(g));
}
#define CP_COMMIT() asm volatile("cp.async.commit_group;" ::: "memory")
#define CP_WAIT(n)  asm volatile("cp.async.wait_group %0;" :: "n"(n) : "memory")

static __device__ __forceinline__ float ex2(float x) {
    float r;
    asm("ex2.approx.f32 %0, %1;" : "=f"(r) : "f"(x));
    return r;
}
static __device__ __forceinline__ uint32_t packf16(float a, float b) {
    uint32_t r;
    asm("cvt.rn.f16x2.f32 %0, %1, %2;" : "=r"(r) : "f"(b), "f"(a));
    return r;
}

// ===================== converts =====================
__global__ __launch_bounds__(256) void convert_qk(const float* __restrict__ q,
                                                  const float* __restrict__ k) {
    int i = blockIdx.x * 256 + threadIdx.x;
    float fq = q[i] * QSCALE;
    __half qh = __float2half(fq);
    g_qhi[i] = qh;
    g_qlo[i] = __float2half(fq - __half2float(qh));
    g_k[i] = __float2half(k[i]);
}
__global__ __launch_bounds__(256) void convert_v(const float* __restrict__ v) {
    __shared__ __half tv[64][65];
    const int h = blockIdx.y, s0 = blockIdx.x * 64, tid = threadIdx.x;
#pragma unroll
    for (int j = 0; j < 16; j++) {
        int i = tid + j * 256, sr = i >> 6, d = i & 63;
        tv[sr][d] = __float2half(v[((size_t)(h * SS + s0 + sr)) * DD + d]);
    }
    __syncthreads();
#pragma unroll
    for (int j = 0; j < 16; j++) {
        int i = tid + j * 256, d = i >> 6, sr = i & 63;
        g_vt[((size_t)(h * DD + d)) * SS + s0 + sr] = tv[sr][d];
    }
}
__global__ __launch_bounds__(256) void convert_mask(const int* __restrict__ m) {
    size_t i = ((size_t)blockIdx.x * 256 + threadIdx.x) * 4;
    int4 v = *(const int4*)(m + i);
    uchar4 b;
    b.x = v.x ? 1 : 0; b.y = v.y ? 1 : 0; b.z = v.z ? 1 : 0; b.w = v.w ? 1 : 0;
    *(uchar4*)(g_mask8 + i) = b;
}

// ===================== fused kernel smem (55.3KB -> 2 blocks/SM) ============
#define F_K0  0        // K buf: fp16 64x144 (9216/buf)
#define F_K1  9216
#define F_V0  18432    // V buf: fp16 64x144 (9216/buf)
#define F_V1  27648
#define F_M0  36864    // mask buf: 128x72 (9216/buf)
#define F_M1  46080
#define F_BYTES 55296

__global__ __launch_bounds__(256, 2) void fused_attn(float* __restrict__ out) {
    extern __shared__ char sm[];
    const uint32_t sb = smem_u32(sm);
    const int h = blockIdx.x, q0 = blockIdx.y * 128, tid = threadIdx.x;
    const int wid = tid >> 5, lane = tid & 31;
    const int lr = lane & 15, lc = lane >> 4;
    const int lam = lane & 3, r4 = lane >> 2;

    // ---- stage Q into smem, load frags into registers, then free smem ----
    {
        const __half* qh = g_qhi + ((size_t)(h * SS + q0)) * DD;
        const __half* ql = g_qlo + ((size_t)(h * SS + q0)) * DD;
#pragma unroll
        for (int j = 0; j < 4; j++) {
            int i = tid + j * 256, row = i >> 3, u = i & 7;
            *(uint4*)(sm + row * 144 + u * 16) = *(const uint4*)(qh + row * DD + u * 8);
            *(uint4*)(sm + 18432 + row * 144 + u * 16) = *(const uint4*)(ql + row * DD + u * 8);
        }
    }
    __syncthreads();
    uint32_t qh_f[4][4], ql_f[4][4];
    {
        const uint32_t qa = sb + (uint32_t)(wid * 16 + lr) * 144 + lc * 16;
#pragma unroll
        for (int ks = 0; ks < 4; ks++) {
            ldsm4(qh_f[ks], qa + ks * 32);
            ldsm4(ql_f[ks], qa + 18432 + ks * 32);
        }
    }
    __syncthreads();

    // ---- prefetch tile 0 ----
    {
        const __half* kk = g_k + ((size_t)(h * SS)) * DD;
        {
            int r0 = tid >> 2, u4 = tid & 3;
            cp16(sb + F_K0 + r0 * 144 + u4 * 32, kk + r0 * DD + u4 * 16);
            cp16(sb + F_K0 + r0 * 144 + u4 * 32 + 16, kk + r0 * DD + u4 * 16 + 8);
        }
        {
            int d = tid >> 2, u = tid & 3;
            cp16(sb + F_V0 + d * 144 + u * 32,
                 g_vt + ((size_t)(h * DD + d)) * SS + u * 16);
            cp16(sb + F_V0 + d * 144 + u * 32 + 16,
                 g_vt + ((size_t)(h * DD + d)) * SS + u * 16 + 8);
        }
#pragma unroll
        for (int j = 0; j < 4; j++) {
            int i = tid + j * 256, row = i >> 3, u = i & 7;
            cp8(sb + F_M0 + row * 72 + u * 8, g_mask8 + (size_t)(q0 + row) * SS + u * 8);
        }
        CP_COMMIT();
    }

    float oacc[8][4];
#pragma unroll
    for (int n = 0; n < 8; n++)
#pragma unroll
        for (int c = 0; c < 4; c++) oacc[n][c] = 0.f;
    float sA = 0.f, sB = 0.f;

    for (int kt = 0; kt < 64; kt++) {
        CP_WAIT(0);
        __syncthreads();
        if (kt < 63) {  // prefetch kt+1
            const int kn = (kt + 1) * 64;
            const int nb = (kt + 1) & 1;
            const uint32_t kb = sb + (nb ? F_K1 : F_K0);
            const uint32_t vb = sb + (nb ? F_V1 : F_V0);
            const uint32_t mb = sb + (nb ? F_M1 : F_M0);
            const __half* kk = g_k + ((size_t)(h * SS + kn)) * DD;
            {
                int r0 = tid >> 2, u4 = tid & 3;
                cp16(kb + r0 * 144 + u4 * 32, kk + r0 * DD + u4 * 16);
                cp16(kb + r0 * 144 + u4 * 32 + 16, kk + r0 * DD + u4 * 16 + 8);
            }
            {
                int d = tid >> 2, u = tid & 3;
                cp16(vb + d * 144 + u * 32,
                     g_vt + ((size_t)(h * DD + d)) * SS + kn + u * 16);
                cp16(vb + d * 144 + u * 32 + 16,
                     g_vt + ((size_t)(h * DD + d)) * SS + kn + u * 16 + 8);
            }
#pragma unroll
            for (int j = 0; j < 4; j++) {
                int i = tid + j * 256, row = i >> 3, u = i & 7;
                cp8(mb + row * 72 + u * 8,
                    g_mask8 + (size_t)(q0 + row) * SS + kn + u * 8);
            }
            CP_COMMIT();
        }
        const uint32_t kbase = sb + ((kt & 1) ? F_K1 : F_K0);
        const uint32_t vbase = sb + ((kt & 1) ? F_V1 : F_V0);
        const char* mbase = sm + ((kt & 1) ? F_M1 : F_M0);
        const int k0 = kt * 64;

        // ---- QK^T (fp16 2-product): warp tile 16q x 64k ----
        float acc[8][4];
#pragma unroll
        for (int n = 0; n < 8; n++)
#pragma unroll
            for (int c = 0; c < 4; c++) acc[n][c] = 0.f;
#pragma unroll
        for (int ks = 0; ks < 4; ks++) {
#pragma unroll
            for (int cg = 0; cg < 4; cg++) {
                uint32_t bk[4];
                ldsm4(bk, kbase + (uint32_t)(cg * 16 + lr) * 144 + lc * 16 + ks * 32);
                mma_f16(acc[2 * cg], qh_f[ks], bk[0], bk[2]);
                mma_f16(acc[2 * cg + 1], qh_f[ks], bk[1], bk[3]);
                mma_f16(acc[2 * cg], ql_f[ks], bk[0], bk[2]);
                mma_f16(acc[2 * cg + 1], ql_f[ks], bk[1], bk[3]);
            }
        }

        // ---- epilogue: mask -> ex2 -> fp16 pack -> p~ STG -> PV ----
        const int rowl = wid * 16 + r4;
#pragma unroll
        for (int cg = 0; cg < 4; cg++) {
            const int cb = cg * 16 + lam * 2;
            uchar2 mA0 = *(const uchar2*)(mbase + rowl * 72 + cb);
            uchar2 mA8 = *(const uchar2*)(mbase + rowl * 72 + cb + 8);
            uchar2 mB0 = *(const uchar2*)(mbase + (rowl + 8) * 72 + cb);
            uchar2 mB8 = *(const uchar2*)(mbase + (rowl + 8) * 72 + cb + 8);
            float eA0 = mA0.x ? 0.f : ex2(acc[2 * cg][0]);
            float eA1 = mA0.y ? 0.f : ex2(acc[2 * cg][1]);
            float eB0 = mB0.x ? 0.f : ex2(acc[2 * cg][2]);
            float eB1 = mB0.y ? 0.f : ex2(acc[2 * cg][3]);
            float eA8 = mA8.x ? 0.f : ex2(acc[2 * cg + 1][0]);
            float eA9 = mA8.y ? 0.f : ex2(acc[2 * cg + 1][1]);
            float eB8 = mB8.x ? 0.f : ex2(acc[2 * cg + 1][2]);
            float eB9 = mB8.y ? 0.f : ex2(acc[2 * cg + 1][3]);
            sA += (eA0 + eA1) + (eA8 + eA9);
            sB += (eB0 + eB1) + (eB8 + eB9);
            uint32_t pa[4];
            pa[0] = packf16(eA0, eA1);
            pa[1] = packf16(eB0, eB1);
            pa[2] = packf16(eA8, eA9);
            pa[3] = packf16(eB8, eB9);
            size_t base = ((size_t)(h * SS + q0 + rowl)) * SS + k0 + cb;
            *(uint32_t*)(g_pt + base) = pa[0];
            *(uint32_t*)(g_pt + base + 8) = pa[2];
            *(uint32_t*)(g_pt + base + 8 * SS) = pa[1];
            *(uint32_t*)(g_pt + base + 8 * SS + 8) = pa[3];
#pragma unroll
            for (int ng = 0; ng < 4; ng++) {
                uint32_t vh[4];
                ldsm4(vh, vbase + (uint32_t)(ng * 16 + lr) * 144 + lc * 16 + cg * 32);
                mma_f16(oacc[2 * ng], pa, vh[0], vh[2]);
                mma_f16(oacc[2 * ng + 1], pa, vh[1], vh[3]);
            }
        }
    }
    // ---- finalize: row sums -> rowinv + normalized out ----
    sA += __shfl_xor_sync(~0u, sA, 1); sA += __shfl_xor_sync(~0u, sA, 2);
    sB += __shfl_xor_sync(~0u, sB, 1); sB += __shfl_xor_sync(~0u, sB, 2);
    const float invA = 1.0f / sA, invB = 1.0f / sB;
    const int rowl = wid * 16 + r4;
    if (lam == 0) {
        g_rowinv[h * SS + q0 + rowl] = invA;
        g_rowinv[h * SS + q0 + rowl + 8] = invB;
    }
#pragma unroll
    for (int nb = 0; nb < 8; nb++) {
        int col = nb * 8 + lam * 2;
        float* op = out + ((size_t)(h * SS + q0 + rowl)) * DD + col;
        *(float2*)op = make_float2(oacc[nb][0] * invA, oacc[nb][1] * invA);
        *(float2*)(op + 8 * DD) = make_float2(oacc[nb][2] * invB, oacc[nb][3] * invB);
    }
}

// ===================== normalize + widen attn (fp16 -> fp32 stream) ========
__global__ __launch_bounds__(256) void norm_attn(float* __restrict__ attn) {
    const int idx = blockIdx.x;
    const float ri = g_rowinv[idx];
    const uint4* src = (const uint4*)(g_pt + (size_t)idx * SS);
    float4* dst = (float4*)(attn + (size_t)idx * SS);
    const int tid = threadIdx.x;
#pragma unroll
    for (int i = 0; i < 2; i++) {
        const int j = tid + i * 256;
        uint4 pp = src[j];
        float2 a = __half22float2(*(__half2*)&pp.x);
        float2 b = __half22float2(*(__half2*)&pp.y);
        float2 c = __half22float2(*(__half2*)&pp.z);
        float2 d = __half22float2(*(__half2*)&pp.w);
        dst[2 * j] = make_float4(a.x * ri, a.y * ri, b.x * ri, b.y * ri);
        dst[2 * j + 1] = make_float4(c.x * ri, c.y * ri, d.x * ri, d.y * ri);
    }
}

// ===================== launch =====================
extern "C" void kernel_launch(void* const* d_in, const int* in_sizes, int n_in,
                              void* d_out, int out_size) {
    const float* q = (const float*)d_in[0];
    const float* k = (const float*)d_in[1];
    const float* v = (const float*)d_in[2];
    const int* mask = (const int*)d_in[3];
    float* out = (float*)d_out;
    float* attn = out + (size_t)HH * SS * DD;

    cudaFuncSetAttribute(fused_attn, cudaFuncAttributeMaxDynamicSharedMemorySize, F_BYTES);

    convert_qk<<<(HH * SS * DD) / 256, 256>>>(q, k);
    convert_v<<<dim3(SS / 64, HH), 256>>>(v);
    convert_mask<<<(SS * SS) / 1024, 256>>>(mask);
    fused_attn<<<dim3(HH, SS / 128), 256, F_BYTES>>>(out);
    norm_attn<<<HH * SS, 256>>>(attn);
}

// round 17
// speedup vs baseline: 1.8727x; 1.1083x over previous
#include <cuda_runtime.h>
#include <cuda_fp16.h>
#include <stdint.h>

#define HH 16
#define SS 4096
#define DD 64
#define QSCALE 0.180336884f   // 0.125 * log2(e)

__device__ __align__(16) __half g_q[HH * SS * DD];
__device__ __align__(16) __half g_k[HH * SS * DD];
__device__ __align__(16) __half g_vt[HH * DD * SS];     // fp16, transposed [h][d][s]
__device__ __align__(16) __half g_pt[(size_t)HH * SS * SS];  // fp16 unnormalized exp
__device__ __align__(16) unsigned char g_mask8[(size_t)SS * SS];
__device__ float g_rowinv[HH * SS];

static __device__ __forceinline__ uint32_t smem_u32(const void* p) {
    uint32_t a;
    asm("{ .reg .u64 t; cvta.to.shared.u64 t, %1; cvt.u32.u64 %0, t; }" : "=r"(a) : "l"(p));
    return a;
}
static __device__ __forceinline__ void ldsm4(uint32_t* r, uint32_t a) {
    asm volatile("ldmatrix.sync.aligned.m8n8.x4.shared.b16 {%0,%1,%2,%3}, [%4];"
        : "=r"(r[0]), "=r"(r[1]), "=r"(r[2]), "=r"(r[3]) : "r"(a));
}
static __device__ __forceinline__ void mma_f16(float* c, const uint32_t* a,
                                               uint32_t b0, uint32_t b1) {
    asm volatile("mma.sync.aligned.m16n8k16.row.col.f32.f16.f16.f32 "
        "{%0,%1,%2,%3}, {%4,%5,%6,%7}, {%8,%9}, {%0,%1,%2,%3};"
        : "+f"(c[0]), "+f"(c[1]), "+f"(c[2]), "+f"(c[3])
        : "r"(a[0]), "r"(a[1]), "r"(a[2]), "r"(a[3]), "r"(b0), "r"(b1));
}
static __device__ __forceinline__ void cp16(uint32_t s, const void* g) {
    asm volatile("cp.async.cg.shared.global [%0], [%1], 16;" :: "r"(s), "l"(g));
}
static __device__ __forceinline__ void cp8(uint32_t s, const void* g) {
    asm volatile("cp.async.ca.shared.global [%0], [%1], 8;" :: "r"(s), "l"(g));
}
#define CP_COMMIT() asm volatile("cp.async.commit_group;" ::: "memory")
#define CP_WAIT(n)  asm volatile("cp.async.wait_group %0;" :: "n"(n) : "memory")

static __device__ __forceinline__ float ex2(float x) {
    float r;
    asm("ex2.approx.f32 %0, %1;" : "=f"(r) : "f"(x));
    return r;
}
static __device__ __forceinline__ uint32_t packf16(float a, float b) {
    uint32_t r;
    asm("cvt.rn.f16x2.f32 %0, %1, %2;" : "=r"(r) : "f"(b), "f"(a));
    return r;
}

// ===================== converts =====================
__global__ __launch_bounds__(256) void convert_qk(const float* __restrict__ q,
                                                  const float* __restrict__ k) {
    int i = blockIdx.x * 256 + threadIdx.x;
    g_q[i] = __float2half(q[i] * QSCALE);
    g_k[i] = __float2half(k[i]);
}
__global__ __launch_bounds__(256) void convert_v(const float* __restrict__ v) {
    __shared__ __half tv[64][65];
    const int h = blockIdx.y, s0 = blockIdx.x * 64, tid = threadIdx.x;
#pragma unroll
    for (int j = 0; j < 16; j++) {
        int i = tid + j * 256, sr = i >> 6, d = i & 63;
        tv[sr][d] = __float2half(v[((size_t)(h * SS + s0 + sr)) * DD + d]);
    }
    __syncthreads();
#pragma unroll
    for (int j = 0; j < 16; j++) {
        int i = tid + j * 256, d = i >> 6, sr = i & 63;
        g_vt[((size_t)(h * DD + d)) * SS + s0 + sr] = tv[sr][d];
    }
}
__global__ __launch_bounds__(256) void convert_mask(const int* __restrict__ m) {
    size_t i = ((size_t)blockIdx.x * 256 + threadIdx.x) * 4;
    int4 v = *(const int4*)(m + i);
    uchar4 b;
    b.x = v.x ? 1 : 0; b.y = v.y ? 1 : 0; b.z = v.z ? 1 : 0; b.w = v.w ? 1 : 0;
    *(uchar4*)(g_mask8 + i) = b;
}

// ===================== fused kernel smem (55.3KB -> 2 blocks/SM) ============
#define F_K0  0        // K buf: fp16 64x144 (9216/buf)
#define F_K1  9216
#define F_V0  18432    // V buf: fp16 64x144 (9216/buf)
#define F_V1  27648
#define F_M0  36864    // mask buf: 128x72 (9216/buf)
#define F_M1  46080
#define F_BYTES 55296

__global__ __launch_bounds__(256, 2) void fused_attn(float* __restrict__ out) {
    extern __shared__ char sm[];
    const uint32_t sb = smem_u32(sm);
    const int h = blockIdx.x, q0 = blockIdx.y * 128, tid = threadIdx.x;
    const int wid = tid >> 5, lane = tid & 31;
    const int lr = lane & 15, lc = lane >> 4;
    const int lam = lane & 3, r4 = lane >> 2;

    // ---- stage Q into smem, load frags into registers, then free smem ----
    {
        const __half* qq = g_q + ((size_t)(h * SS + q0)) * DD;
#pragma unroll
        for (int j = 0; j < 4; j++) {
            int i = tid + j * 256, row = i >> 3, u = i & 7;
            *(uint4*)(sm + row * 144 + u * 16) = *(const uint4*)(qq + row * DD + u * 8);
        }
    }
    __syncthreads();
    uint32_t q_f[4][4];
    {
        const uint32_t qa = sb + (uint32_t)(wid * 16 + lr) * 144 + lc * 16;
#pragma unroll
        for (int ks = 0; ks < 4; ks++) ldsm4(q_f[ks], qa + ks * 32);
    }
    __syncthreads();

    // ---- prefetch tile 0 ----
    {
        const __half* kk = g_k + ((size_t)(h * SS)) * DD;
        {
            int r0 = tid >> 2, u4 = tid & 3;
            cp16(sb + F_K0 + r0 * 144 + u4 * 32, kk + r0 * DD + u4 * 16);
            cp16(sb + F_K0 + r0 * 144 + u4 * 32 + 16, kk + r0 * DD + u4 * 16 + 8);
        }
        {
            int d = tid >> 2, u = tid & 3;
            cp16(sb + F_V0 + d * 144 + u * 32,
                 g_vt + ((size_t)(h * DD + d)) * SS + u * 16);
            cp16(sb + F_V0 + d * 144 + u * 32 + 16,
                 g_vt + ((size_t)(h * DD + d)) * SS + u * 16 + 8);
        }
#pragma unroll
        for (int j = 0; j < 4; j++) {
            int i = tid + j * 256, row = i >> 3, u = i & 7;
            cp8(sb + F_M0 + row * 72 + u * 8, g_mask8 + (size_t)(q0 + row) * SS + u * 8);
        }
        CP_COMMIT();
    }

    float oacc[8][4];
#pragma unroll
    for (int n = 0; n < 8; n++)
#pragma unroll
        for (int c = 0; c < 4; c++) oacc[n][c] = 0.f;
    float sA = 0.f, sB = 0.f;

    for (int kt = 0; kt < 64; kt++) {
        CP_WAIT(0);
        __syncthreads();
        if (kt < 63) {  // prefetch kt+1
            const int kn = (kt + 1) * 64;
            const int nb = (kt + 1) & 1;
            const uint32_t kb = sb + (nb ? F_K1 : F_K0);
            const uint32_t vb = sb + (nb ? F_V1 : F_V0);
            const uint32_t mb = sb + (nb ? F_M1 : F_M0);
            const __half* kk = g_k + ((size_t)(h * SS + kn)) * DD;
            {
                int r0 = tid >> 2, u4 = tid & 3;
                cp16(kb + r0 * 144 + u4 * 32, kk + r0 * DD + u4 * 16);
                cp16(kb + r0 * 144 + u4 * 32 + 16, kk + r0 * DD + u4 * 16 + 8);
            }
            {
                int d = tid >> 2, u = tid & 3;
                cp16(vb + d * 144 + u * 32,
                     g_vt + ((size_t)(h * DD + d)) * SS + kn + u * 16);
                cp16(vb + d * 144 + u * 32 + 16,
                     g_vt + ((size_t)(h * DD + d)) * SS + kn + u * 16 + 8);
            }
#pragma unroll
            for (int j = 0; j < 4; j++) {
                int i = tid + j * 256, row = i >> 3, u = i & 7;
                cp8(mb + row * 72 + u * 8,
                    g_mask8 + (size_t)(q0 + row) * SS + kn + u * 8);
            }
            CP_COMMIT();
        }
        const uint32_t kbase = sb + ((kt & 1) ? F_K1 : F_K0);
        const uint32_t vbase = sb + ((kt & 1) ? F_V1 : F_V0);
        const char* mbase = sm + ((kt & 1) ? F_M1 : F_M0);
        const int k0 = kt * 64;

        // ---- QK^T (fp16 single product): warp tile 16q x 64k ----
        float acc[8][4];
#pragma unroll
        for (int n = 0; n < 8; n++)
#pragma unroll
            for (int c = 0; c < 4; c++) acc[n][c] = 0.f;
#pragma unroll
        for (int ks = 0; ks < 4; ks++) {
#pragma unroll
            for (int cg = 0; cg < 4; cg++) {
                uint32_t bk[4];
                ldsm4(bk, kbase + (uint32_t)(cg * 16 + lr) * 144 + lc * 16 + ks * 32);
                mma_f16(acc[2 * cg], q_f[ks], bk[0], bk[2]);
                mma_f16(acc[2 * cg + 1], q_f[ks], bk[1], bk[3]);
            }
        }

        // ---- epilogue: mask -> ex2 -> fp16 pack -> p~ STG -> PV ----
        const int rowl = wid * 16 + r4;
#pragma unroll
        for (int cg = 0; cg < 4; cg++) {
            const int cb = cg * 16 + lam * 2;
            uchar2 mA0 = *(const uchar2*)(mbase + rowl * 72 + cb);
            uchar2 mA8 = *(const uchar2*)(mbase + rowl * 72 + cb + 8);
            uchar2 mB0 = *(const uchar2*)(mbase + (rowl + 8) * 72 + cb);
            uchar2 mB8 = *(const uchar2*)(mbase + (rowl + 8) * 72 + cb + 8);
            float eA0 = mA0.x ? 0.f : ex2(acc[2 * cg][0]);
            float eA1 = mA0.y ? 0.f : ex2(acc[2 * cg][1]);
            float eB0 = mB0.x ? 0.f : ex2(acc[2 * cg][2]);
            float eB1 = mB0.y ? 0.f : ex2(acc[2 * cg][3]);
            float eA8 = mA8.x ? 0.f : ex2(acc[2 * cg + 1][0]);
            float eA9 = mA8.y ? 0.f : ex2(acc[2 * cg + 1][1]);
            float eB8 = mB8.x ? 0.f : ex2(acc[2 * cg + 1][2]);
            float eB9 = mB8.y ? 0.f : ex2(acc[2 * cg + 1][3]);
            sA += (eA0 + eA1) + (eA8 + eA9);
            sB += (eB0 + eB1) + (eB8 + eB9);
            uint32_t pa[4];
            pa[0] = packf16(eA0, eA1);
            pa[1] = packf16(eB0, eB1);
            pa[2] = packf16(eA8, eA9);
            pa[3] = packf16(eB8, eB9);
            size_t base = ((size_t)(h * SS + q0 + rowl)) * SS + k0 + cb;
            *(uint32_t*)(g_pt + base) = pa[0];
            *(uint32_t*)(g_pt + base + 8) = pa[2];
            *(uint32_t*)(g_pt + base + 8 * SS) = pa[1];
            *(uint32_t*)(g_pt + base + 8 * SS + 8) = pa[3];
#pragma unroll
            for (int ng = 0; ng < 4; ng++) {
                uint32_t vh[4];
                ldsm4(vh, vbase + (uint32_t)(ng * 16 + lr) * 144 + lc * 16 + cg * 32);
                mma_f16(oacc[2 * ng], pa, vh[0], vh[2]);
                mma_f16(oacc[2 * ng + 1], pa, vh[1], vh[3]);
            }
        }
    }
    // ---- finalize: row sums -> rowinv + normalized out ----
    sA += __shfl_xor_sync(~0u, sA, 1); sA += __shfl_xor_sync(~0u, sA, 2);
    sB += __shfl_xor_sync(~0u, sB, 1); sB += __shfl_xor_sync(~0u, sB, 2);
    const float invA = 1.0f / sA, invB = 1.0f / sB;
    const int rowl = wid * 16 + r4;
    if (lam == 0) {
        g_rowinv[h * SS + q0 + rowl] = invA;
        g_rowinv[h * SS + q0 + rowl + 8] = invB;
    }
#pragma unroll
    for (int nb = 0; nb < 8; nb++) {
        int col = nb * 8 + lam * 2;
        float* op = out + ((size_t)(h * SS + q0 + rowl)) * DD + col;
        *(float2*)op = make_float2(oacc[nb][0] * invA, oacc[nb][1] * invA);
        *(float2*)(op + 8 * DD) = make_float2(oacc[nb][2] * invB, oacc[nb][3] * invB);
    }
}

// ===================== normalize + widen attn (fp16 -> fp32 stream) ========
__global__ __launch_bounds__(256) void norm_attn(float* __restrict__ attn) {
    const int idx = blockIdx.x;
    const float ri = g_rowinv[idx];
    const uint4* src = (const uint4*)(g_pt + (size_t)idx * SS);
    float4* dst = (float4*)(attn + (size_t)idx * SS);
    const int tid = threadIdx.x;
#pragma unroll
    for (int i = 0; i < 2; i++) {
        const int j = tid + i * 256;
        uint4 pp = src[j];
        float2 a = __half22float2(*(__half2*)&pp.x);
        float2 b = __half22float2(*(__half2*)&pp.y);
        float2 c = __half22float2(*(__half2*)&pp.z);
        float2 d = __half22float2(*(__half2*)&pp.w);
        dst[2 * j] = make_float4(a.x * ri, a.y * ri, b.x * ri, b.y * ri);
        dst[2 * j + 1] = make_float4(c.x * ri, c.y * ri, d.x * ri, d.y * ri);
    }
}

// ===================== launch =====================
extern "C" void kernel_launch(void* const* d_in, const int* in_sizes, int n_in,
                              void* d_out, int out_size) {
    const float* q = (const float*)d_in[0];
    const float* k = (const float*)d_in[1];
    const float* v = (const float*)d_in[2];
    const int* mask = (const int*)d_in[3];
    float* out = (float*)d_out;
    float* attn = out + (size_t)HH * SS * DD;

    cudaFuncSetAttribute(fused_attn, cudaFuncAttributeMaxDynamicSharedMemorySize, F_BYTES);

    convert_qk<<<(HH * SS * DD) / 256, 256>>>(q, k);
    convert_v<<<dim3(SS / 64, HH), 256>>>(v);
    convert_mask<<<(SS * SS) / 1024, 256>>>(mask);
    fused_attn<<<dim3(HH, SS / 128), 256, F_BYTES>>>(out);
    norm_attn<<<HH * SS, 256>>>(attn);
}